// round 1
// baseline (speedup 1.0000x reference)
#include <cuda_runtime.h>

// Problem constants
#define BB  8
#define NN  8192
#define CC  128
#define HH  8
#define DHH 64
#define GG  32
#define SS  16              // n-split for encode phase
#define NSS (NN/SS)         // 512 rows per split

typedef unsigned long long u64;

// Scratch (device globals: no allocation allowed)
__device__ float g_Yp[(size_t)SS*BB*HH*GG*CC];   // 16 MB partials
__device__ float g_t [(size_t)BB*HH*GG*CC];      // 1 MB
__device__ float g_sin[HH*GG];                   // sum_n inv_in

// ---- packed fp32x2 helpers (FFMA2 is PTX-only on sm_103a) ----
__device__ __forceinline__ u64 pack2(float lo, float hi) {
    u64 r; asm("mov.b64 %0, {%1, %2};" : "=l"(r) : "f"(lo), "f"(hi)); return r;
}
__device__ __forceinline__ void unpack2(u64 v, float& lo, float& hi) {
    asm("mov.b64 {%0, %1}, %2;" : "=f"(lo), "=f"(hi) : "l"(v));
}
__device__ __forceinline__ void ffma2(u64& d, u64 a, u64 b) {
    asm("fma.rn.f32x2 %0, %1, %2, %0;" : "+l"(d) : "l"(a), "l"(b));
}

// ============================================================
// K0: s_in[h,g] = sum_n inv_in[h,n,g]   (for the b_in bias path)
// ============================================================
__global__ __launch_bounds__(256) void kS(const float* __restrict__ inv_in) {
    int h = blockIdx.x, tid = threadIdx.x;
    int lane = tid & 31, warp = tid >> 5;
    float acc[32];
#pragma unroll
    for (int g = 0; g < 32; g++) acc[g] = 0.f;
    for (int n = tid; n < NN; n += 256) {
        const float4* r = (const float4*)(inv_in + ((size_t)h * NN + n) * GG);
#pragma unroll
        for (int q = 0; q < 8; q++) {
            float4 v = r[q];
            acc[4*q+0] += v.x; acc[4*q+1] += v.y; acc[4*q+2] += v.z; acc[4*q+3] += v.w;
        }
    }
#pragma unroll
    for (int off = 16; off; off >>= 1)
#pragma unroll
        for (int g = 0; g < 32; g++) acc[g] += __shfl_xor_sync(0xffffffffu, acc[g], off);
    __shared__ float wred[8][32];
    if (lane == 0)
#pragma unroll
        for (int g = 0; g < 32; g++) wred[warp][g] = acc[g];
    __syncthreads();
    if (tid < 32) {
        float s = 0.f;
#pragma unroll
        for (int w = 0; w < 8; w++) s += wred[w][tid];
        g_sin[h * 32 + tid] = s;
    }
}

// ============================================================
// KA: encode partials Yp[s,b,h,g,c] = sum_{n in split s} x[b,n,c]*inv_in[h,n,g]
// grid (SS, HH, BB), 128 threads. Tile: 32g x 128c, per-thread 2g x 16c.
// ============================================================
__global__ __launch_bounds__(128) void kA(const float* __restrict__ x,
                                          const float* __restrict__ inv_in) {
    int s = blockIdx.x, h = blockIdx.y, b = blockIdx.z;
    __shared__ float xs[32 * 128];   // 16 KB
    __shared__ float ivs[32 * 32];   // 4 KB
    int tid = threadIdx.x;
    int tx = tid & 7, ty = tid >> 3;
    int cbase = tx * 4;              // c = cbase + j*32, j<4 (4 floats each)
    int g0 = ty * 2;

    u64 acc0[4][2], acc1[4][2];
#pragma unroll
    for (int j = 0; j < 4; j++) {
        acc0[j][0] = acc0[j][1] = 0ull;
        acc1[j][0] = acc1[j][1] = 0ull;
    }

    int n0 = s * NSS;
    for (int it = 0; it < NSS / 32; ++it) {
        int nb = n0 + it * 32;
        // flat coalesced fills (both src/dst contiguous)
        const float4* xsrc = (const float4*)(x + ((size_t)b * NN + nb) * CC);
        float4* xd = (float4*)xs;
#pragma unroll
        for (int k = 0; k < 8; k++) xd[tid + k * 128] = xsrc[tid + k * 128];
        const float4* isrc = (const float4*)(inv_in + ((size_t)h * NN + nb) * GG);
        float4* id = (float4*)ivs;
#pragma unroll
        for (int k = 0; k < 2; k++) id[tid + k * 128] = isrc[tid + k * 128];
        __syncthreads();

#pragma unroll 8
        for (int n = 0; n < 32; n++) {
            float iv0 = ivs[n * 32 + g0];
            float iv1 = ivs[n * 32 + g0 + 1];
            u64 a0 = pack2(iv0, iv0), a1 = pack2(iv1, iv1);
#pragma unroll
            for (int j = 0; j < 4; j++) {
                ulonglong2 p = *(const ulonglong2*)(xs + n * 128 + cbase + j * 32);
                ffma2(acc0[j][0], a0, p.x); ffma2(acc0[j][1], a0, p.y);
                ffma2(acc1[j][0], a1, p.x); ffma2(acc1[j][1], a1, p.y);
            }
        }
        __syncthreads();
    }

    size_t base0 = ((((size_t)s * BB + b) * HH + h) * GG + g0) * CC + cbase;
#pragma unroll
    for (int j = 0; j < 4; j++) {
        ulonglong2 v0; v0.x = acc0[j][0]; v0.y = acc0[j][1];
        *(ulonglong2*)(g_Yp + base0 + j * 32) = v0;
        ulonglong2 v1; v1.x = acc1[j][0]; v1.y = acc1[j][1];
        *(ulonglong2*)(g_Yp + base0 + CC + j * 32) = v1;
    }
}

// ============================================================
// KB: middle pipeline per (b,h): reduce Yp -> Y; spec = Y@W_in_h + bias;
//     LayerNorm over (G,DH); @mlp_w; @W_out_h -> t[b,h,g,c]
// grid (HH, BB), 256 threads.
// ============================================================
__global__ __launch_bounds__(256) void kB(const float* __restrict__ W_in,
                                          const float* __restrict__ b_in,
                                          const float* __restrict__ mlp_w,
                                          const float* __restrict__ ln_g,
                                          const float* __restrict__ ln_b,
                                          const float* __restrict__ W_out) {
    int h = blockIdx.x, b = blockIdx.y;
    __shared__ float bufA[4096];  // Y[g][c] -> mlp_w -> W_out chunk
    __shared__ float bufB[2048];  // W_in chunk -> normalized spec
    __shared__ float bufC[2048];  // m[g][o]
    __shared__ float red[16];
    int tid = threadIdx.x;

    // S1: reduce partials: Y[g*128+c]
#pragma unroll
    for (int k = 0; k < 16; k++) {
        int idx = tid + k * 256;
        float ssum = 0.f;
#pragma unroll
        for (int s = 0; s < SS; s++)
            ssum += g_Yp[(((size_t)s * BB + b) * HH + h) * 4096 + idx];
        bufA[idx] = ssum;
    }
    __syncthreads();

    // S2: spec_raw[g][d] = sum_c Y[g][c] * W_in[c][h*64+d]
    int d = tid & 63, g4 = tid >> 6;     // entries g = g4 + 4k
    float sp[8];
#pragma unroll
    for (int k = 0; k < 8; k++) sp[k] = 0.f;
    for (int cc = 0; cc < 4; cc++) {
#pragma unroll
        for (int j = 0; j < 8; j++) {
            int idx = tid + j * 256;
            int r = idx >> 6, dd = idx & 63;
            bufB[idx] = W_in[((size_t)(cc * 32 + r)) * (HH * DHH) + h * 64 + dd];
        }
        __syncthreads();
#pragma unroll
        for (int i = 0; i < 32; i++) {
            float w = bufB[i * 64 + d];
            int c = cc * 32 + i;
#pragma unroll
            for (int k = 0; k < 8; k++) sp[k] += bufA[(g4 + 4 * k) * 128 + c] * w;
        }
        __syncthreads();
    }

    // bias via s_in
    float bv = b_in[h * 64 + d];
#pragma unroll
    for (int k = 0; k < 8; k++) sp[k] += bv * g_sin[h * 32 + (g4 + 4 * k)];

    // LayerNorm over all 2048 (g,d)
    float lsum = 0.f, lsq = 0.f;
#pragma unroll
    for (int k = 0; k < 8; k++) { lsum += sp[k]; lsq += sp[k] * sp[k]; }
#pragma unroll
    for (int off = 16; off; off >>= 1) {
        lsum += __shfl_xor_sync(0xffffffffu, lsum, off);
        lsq  += __shfl_xor_sync(0xffffffffu, lsq,  off);
    }
    int warp = tid >> 5, lane = tid & 31;
    if (lane == 0) { red[warp] = lsum; red[8 + warp] = lsq; }
    __syncthreads();
    float tsum = 0.f, tsq = 0.f;
#pragma unroll
    for (int w = 0; w < 8; w++) { tsum += red[w]; tsq += red[8 + w]; }
    float mu = tsum * (1.f / 2048.f);
    float var = tsq * (1.f / 2048.f) - mu * mu;
    float rstd = rsqrtf(var + 1e-5f);
    __syncthreads();
#pragma unroll
    for (int k = 0; k < 8; k++) {
        int g = g4 + 4 * k;
        float v = (sp[k] - mu) * rstd * ln_g[g * 64 + d] + ln_b[g * 64 + d];
        bufB[g * 64 + d] = v;
    }
    __syncthreads();

    // S4: m[g][o] = sum_d spec_n[g][d] * mlp_w[d][o]
#pragma unroll
    for (int j = 0; j < 16; j++) bufA[tid + j * 256] = mlp_w[tid + j * 256];
    __syncthreads();
    int o = d;
    float m[8];
#pragma unroll
    for (int k = 0; k < 8; k++) m[k] = 0.f;
#pragma unroll
    for (int dd = 0; dd < 64; dd++) {
        float w = bufA[dd * 64 + o];
#pragma unroll
        for (int k = 0; k < 8; k++) m[k] += bufB[(g4 + 4 * k) * 64 + dd] * w;
    }
#pragma unroll
    for (int k = 0; k < 8; k++) bufC[(g4 + 4 * k) * 64 + o] = m[k];
    __syncthreads();

    // S5: t[g][c] = sum_o m[g][o] * W_out[h*64+o][c]
    int c = tid & 127, g2 = tid >> 7;    // entries g = g2 + 2k
    float tacc[16];
#pragma unroll
    for (int k = 0; k < 16; k++) tacc[k] = 0.f;
    for (int oc = 0; oc < 2; oc++) {
#pragma unroll
        for (int j = 0; j < 16; j++) {
            int idx = tid + j * 256;
            int r = idx >> 7, c2 = idx & 127;
            bufA[idx] = W_out[((size_t)(h * 64 + oc * 32 + r)) * CC + c2];
        }
        __syncthreads();
#pragma unroll
        for (int i = 0; i < 32; i++) {
            float w = bufA[i * 128 + c];
            int oo = oc * 32 + i;
#pragma unroll
            for (int k = 0; k < 16; k++) tacc[k] += bufC[(g2 + 2 * k) * 64 + oo] * w;
        }
        __syncthreads();
    }
    size_t tb = (((size_t)b * HH + h) * GG) * CC;
#pragma unroll
    for (int k = 0; k < 16; k++) g_t[tb + (size_t)(g2 + 2 * k) * CC + c] = tacc[k];
}

// ============================================================
// KC: decode: out[b,n,c] = b_out[c] + sum_{h,g} t[b,h,g,c]*inv_out[h,n,g]
// grid (NN/64, BB), 256 threads. Tile: 64n x 128c, per-thread 2n x 16c.
// ============================================================
__global__ __launch_bounds__(256) void kC(const float* __restrict__ inv_out,
                                          const float* __restrict__ b_out,
                                          float* __restrict__ out) {
    int nt = blockIdx.x, b = blockIdx.y;
    __shared__ float ts[32 * 128];     // 16 KB
    __shared__ float iv2[32 * 65];     // transposed [g][n], padded: 8.3 KB
    int tid = threadIdx.x;
    int tx = tid & 7, ty = tid >> 3;
    int cbase = tx * 4;                // c = cbase + j*32
    int r0 = ty * 2;                   // rows r0, r0+1
    int nbase = nt * 64;

    u64 accA[4][2], accB[4][2];
#pragma unroll
    for (int j = 0; j < 4; j++) {
        accA[j][0] = accA[j][1] = 0ull;
        accB[j][0] = accB[j][1] = 0ull;
    }

    for (int h = 0; h < HH; h++) {
        const float4* tsrc = (const float4*)(g_t + (((size_t)b * HH + h) * GG) * CC);
        float4* td = (float4*)ts;
#pragma unroll
        for (int k = 0; k < 4; k++) td[tid + k * 256] = tsrc[tid + k * 256];
        // transpose inv_out tile into [g][n] with pad-65 rows
        const float* isrc = inv_out + ((size_t)h * NN + nbase) * GG;
#pragma unroll
        for (int k = 0; k < 8; k++) {
            int idx = tid + k * 256;     // idx = r*32 + g
            int r = idx >> 5, g = idx & 31;
            iv2[g * 65 + r] = isrc[idx];
        }
        __syncthreads();

#pragma unroll 8
        for (int g = 0; g < 32; g++) {
            float i0 = iv2[g * 65 + r0];
            float i1 = iv2[g * 65 + r0 + 1];
            u64 a0 = pack2(i0, i0), a1 = pack2(i1, i1);
#pragma unroll
            for (int j = 0; j < 4; j++) {
                ulonglong2 p = *(const ulonglong2*)(ts + g * 128 + cbase + j * 32);
                ffma2(accA[j][0], a0, p.x); ffma2(accA[j][1], a0, p.y);
                ffma2(accB[j][0], a1, p.x); ffma2(accB[j][1], a1, p.y);
            }
        }
        __syncthreads();
    }

    // epilogue: add bias, store
    float* orow0 = out + ((size_t)b * NN + nbase + r0) * CC + cbase;
    float* orow1 = orow0 + CC;
#pragma unroll
    for (int j = 0; j < 4; j++) {
        float4 bo = *(const float4*)(b_out + cbase + j * 32);
        float f0, f1, f2, f3;
        unpack2(accA[j][0], f0, f1); unpack2(accA[j][1], f2, f3);
        float4 v0; v0.x = f0 + bo.x; v0.y = f1 + bo.y; v0.z = f2 + bo.z; v0.w = f3 + bo.w;
        *(float4*)(orow0 + j * 32) = v0;
        unpack2(accB[j][0], f0, f1); unpack2(accB[j][1], f2, f3);
        float4 v1; v1.x = f0 + bo.x; v1.y = f1 + bo.y; v1.z = f2 + bo.z; v1.w = f3 + bo.w;
        *(float4*)(orow1 + j * 32) = v1;
    }
}

// ============================================================
extern "C" void kernel_launch(void* const* d_in, const int* in_sizes, int n_in,
                              void* d_out, int out_size) {
    const float* x      = (const float*)d_in[0];
    const float* W_in   = (const float*)d_in[1];
    const float* b_in   = (const float*)d_in[2];
    const float* mlp_w  = (const float*)d_in[3];
    const float* ln_g   = (const float*)d_in[4];
    const float* ln_b   = (const float*)d_in[5];
    const float* W_out  = (const float*)d_in[6];
    const float* b_out  = (const float*)d_in[7];
    const float* inv_in = (const float*)d_in[8];
    const float* inv_out= (const float*)d_in[9];
    float* out = (float*)d_out;

    kS<<<HH, 256>>>(inv_in);
    kA<<<dim3(SS, HH, BB), 128>>>(x, inv_in);
    kB<<<dim3(HH, BB), 256>>>(W_in, b_in, mlp_w, ln_g, ln_b, W_out);
    kC<<<dim3(NN / 64, BB), 256>>>(inv_out, b_out, out);
}

// round 2
// speedup vs baseline: 1.3913x; 1.3913x over previous
#include <cuda_runtime.h>

// Problem constants
#define BB  8
#define NN  8192
#define CC  128
#define HH  8
#define DHH 64
#define GG  32
#define SS  32              // n-splits for encode phase
#define NSS (NN/SS)         // 256 rows per split

typedef unsigned long long u64;

// Scratch (device globals: no allocation allowed)
__device__ float g_Yp[(size_t)SS*BB*HH*GG*CC];   // 33.5 MB partials
__device__ float g_Y [(size_t)BB*HH*GG*CC];      // 1 MB reduced Y
__device__ float g_t [(size_t)BB*HH*GG*CC];      // 1 MB middle output
__device__ float g_sinp[16*HH*GG];               // chunked partial sums of inv_in

// ---- packed fp32x2 helpers (FFMA2 is PTX-only on sm_103a) ----
__device__ __forceinline__ u64 pack2(float lo, float hi) {
    u64 r; asm("mov.b64 %0, {%1, %2};" : "=l"(r) : "f"(lo), "f"(hi)); return r;
}
__device__ __forceinline__ void unpack2(u64 v, float& lo, float& hi) {
    asm("mov.b64 {%0, %1}, %2;" : "=f"(lo), "=f"(hi) : "l"(v));
}
__device__ __forceinline__ void ffma2(u64& d, u64 a, u64 b) {
    asm("fma.rn.f32x2 %0, %1, %2, %0;" : "+l"(d) : "l"(a), "l"(b));
}

// ============================================================
// kS: chunk partials of s_in[h,g] = sum_n inv_in[h,n,g]
// grid (HH, 16), 256 threads; chunk = 512 n rows.
// ============================================================
__global__ __launch_bounds__(256) void kS(const float* __restrict__ inv_in) {
    int h = blockIdx.x, ch = blockIdx.y, tid = threadIdx.x;
    int lane = tid & 31, warp = tid >> 5;
    float acc[32];
#pragma unroll
    for (int g = 0; g < 32; g++) acc[g] = 0.f;
    int n0 = ch * 512;
    for (int n = n0 + tid; n < n0 + 512; n += 256) {
        const float4* r = (const float4*)(inv_in + ((size_t)h * NN + n) * GG);
#pragma unroll
        for (int q = 0; q < 8; q++) {
            float4 v = r[q];
            acc[4*q+0] += v.x; acc[4*q+1] += v.y; acc[4*q+2] += v.z; acc[4*q+3] += v.w;
        }
    }
#pragma unroll
    for (int off = 16; off; off >>= 1)
#pragma unroll
        for (int g = 0; g < 32; g++) acc[g] += __shfl_xor_sync(0xffffffffu, acc[g], off);
    __shared__ float wred[8][32];
    if (lane == 0)
#pragma unroll
        for (int g = 0; g < 32; g++) wred[warp][g] = acc[g];
    __syncthreads();
    if (tid < 32) {
        float s = 0.f;
#pragma unroll
        for (int w = 0; w < 8; w++) s += wred[w][tid];
        g_sinp[ch * (HH * GG) + h * 32 + tid] = s;
    }
}

// ============================================================
// kA: encode partials Yp[s,b,h,g,c] += x[b,n,c]*inv_in[h,n,g] over n-split s.
// grid (SS, HH/4, BB), 256 threads. CTA tile: 4h x 32g (=128 rows) x 128c.
// Per thread: 8 rows x 8 cols, 32 FFMA2 per k-step.
// ============================================================
__global__ __launch_bounds__(256, 2) void kA(const float* __restrict__ x,
                                             const float* __restrict__ inv_in) {
    int s = blockIdx.x, hq = blockIdx.y, b = blockIdx.z;
    __shared__ float xs[32 * 128];    // 16 KB: [n][c]
    __shared__ float ivs[32 * 128];   // 16 KB: [n][h'*32+g]
    int tid = threadIdx.x;
    int tx = tid & 15, ty = tid >> 4;
    int c0 = tx * 4;                  // c in {c0..c0+3} U {c0+64..c0+67}
    int r0 = ty * 8;                  // rows r0..r0+7 (row = h'*32 + g)
    int h0 = hq * 4;

    u64 acc[8][4];
#pragma unroll
    for (int i = 0; i < 8; i++)
#pragma unroll
        for (int j = 0; j < 4; j++) acc[i][j] = 0ull;

    int n0 = s * NSS;
    for (int kt = 0; kt < NSS / 32; ++kt) {
        int nb = n0 + kt * 32;
        const float4* xsrc = (const float4*)(x + ((size_t)b * NN + nb) * CC);
        float4* xd = (float4*)xs;
#pragma unroll
        for (int j = 0; j < 4; j++) xd[tid + j * 256] = xsrc[tid + j * 256];
#pragma unroll
        for (int j = 0; j < 4; j++) {
            int i4 = tid + j * 256;            // 0..1023
            int hp = i4 >> 8, rem = i4 & 255;  // h' block of 256 float4
            int n = rem >> 3, gq = rem & 7;
            ((float4*)ivs)[n * 32 + hp * 8 + gq] =
                *(const float4*)(inv_in + ((size_t)(h0 + hp) * NN + nb + n) * GG + gq * 4);
        }
        __syncthreads();

#pragma unroll 2
        for (int n = 0; n < 32; n++) {
            const float* ivr = ivs + n * 128 + r0;
            u64 a[8];
#pragma unroll
            for (int i = 0; i < 8; i++) { float v = ivr[i]; a[i] = pack2(v, v); }
            const float* xr = xs + n * 128 + c0;
            ulonglong2 p0 = *(const ulonglong2*)(xr);
            ulonglong2 p1 = *(const ulonglong2*)(xr + 64);
#pragma unroll
            for (int i = 0; i < 8; i++) {
                ffma2(acc[i][0], a[i], p0.x);
                ffma2(acc[i][1], a[i], p0.y);
                ffma2(acc[i][2], a[i], p1.x);
                ffma2(acc[i][3], a[i], p1.y);
            }
        }
        __syncthreads();
    }

#pragma unroll
    for (int i = 0; i < 8; i++) {
        int r = r0 + i;
        int hp = r >> 5, g = r & 31;
        size_t base = ((((size_t)s * BB + b) * HH + (h0 + hp)) * GG + g) * CC + c0;
        ulonglong2 v0; v0.x = acc[i][0]; v0.y = acc[i][1];
        *(ulonglong2*)(g_Yp + base) = v0;
        ulonglong2 v1; v1.x = acc[i][2]; v1.y = acc[i][3];
        *(ulonglong2*)(g_Yp + base + 64) = v1;
    }
}

// ============================================================
// kR: reduce partials: g_Y[idx] = sum_s g_Yp[s][idx]
// grid 256, 256 threads, float4 per thread.
// ============================================================
__global__ __launch_bounds__(256) void kR() {
    int i4 = blockIdx.x * 256 + threadIdx.x;   // 0..65535
    const float4* p = (const float4*)g_Yp;
    float4 s = make_float4(0.f, 0.f, 0.f, 0.f);
    const size_t stride4 = (size_t)BB * HH * GG * CC / 4;
#pragma unroll
    for (int ss = 0; ss < SS; ss++) {
        float4 v = p[(size_t)ss * stride4 + i4];
        s.x += v.x; s.y += v.y; s.z += v.z; s.w += v.w;
    }
    ((float4*)g_Y)[i4] = s;
}

// ============================================================
// kB: middle per (b,h): spec = Y@W_in_h + bias; LN over (G,DH); @mlp_w;
//     @W_out_h -> t[b,h,g,c].   grid (HH, BB), 256 threads.
// ============================================================
__global__ __launch_bounds__(256) void kB(const float* __restrict__ W_in,
                                          const float* __restrict__ b_in,
                                          const float* __restrict__ mlp_w,
                                          const float* __restrict__ ln_g,
                                          const float* __restrict__ ln_b,
                                          const float* __restrict__ W_out) {
    int h = blockIdx.x, b = blockIdx.y;
    __shared__ float bufA[4096];
    __shared__ float bufB[2048];
    __shared__ float bufC[2048];
    __shared__ float red[16];
    int tid = threadIdx.x;

    // S1: load reduced Y[g*128+c]
#pragma unroll
    for (int k = 0; k < 16; k++) {
        int idx = tid + k * 256;
        bufA[idx] = g_Y[((size_t)(b * HH + h)) * 4096 + idx];
    }
    __syncthreads();

    // S2: spec_raw[g][d] = sum_c Y[g][c] * W_in[c][h*64+d]
    int d = tid & 63, g4 = tid >> 6;
    float sp[8];
#pragma unroll
    for (int k = 0; k < 8; k++) sp[k] = 0.f;
    for (int cc = 0; cc < 4; cc++) {
#pragma unroll
        for (int j = 0; j < 8; j++) {
            int idx = tid + j * 256;
            int r = idx >> 6, dd = idx & 63;
            bufB[idx] = W_in[((size_t)(cc * 32 + r)) * (HH * DHH) + h * 64 + dd];
        }
        __syncthreads();
#pragma unroll
        for (int i = 0; i < 32; i++) {
            float w = bufB[i * 64 + d];
            int c = cc * 32 + i;
#pragma unroll
            for (int k = 0; k < 8; k++) sp[k] += bufA[(g4 + 4 * k) * 128 + c] * w;
        }
        __syncthreads();
    }

    // bias via chunked s_in partials
    float bv = b_in[h * 64 + d];
#pragma unroll
    for (int k = 0; k < 8; k++) {
        int g = g4 + 4 * k;
        float sv = 0.f;
#pragma unroll
        for (int ch = 0; ch < 16; ch++) sv += g_sinp[ch * (HH * GG) + h * 32 + g];
        sp[k] += bv * sv;
    }

    // LayerNorm over all 2048 (g,d)
    float lsum = 0.f, lsq = 0.f;
#pragma unroll
    for (int k = 0; k < 8; k++) { lsum += sp[k]; lsq += sp[k] * sp[k]; }
#pragma unroll
    for (int off = 16; off; off >>= 1) {
        lsum += __shfl_xor_sync(0xffffffffu, lsum, off);
        lsq  += __shfl_xor_sync(0xffffffffu, lsq,  off);
    }
    int warp = tid >> 5, lane = tid & 31;
    if (lane == 0) { red[warp] = lsum; red[8 + warp] = lsq; }
    __syncthreads();
    float tsum = 0.f, tsq = 0.f;
#pragma unroll
    for (int w = 0; w < 8; w++) { tsum += red[w]; tsq += red[8 + w]; }
    float mu = tsum * (1.f / 2048.f);
    float var = tsq * (1.f / 2048.f) - mu * mu;
    float rstd = rsqrtf(var + 1e-5f);
    __syncthreads();
#pragma unroll
    for (int k = 0; k < 8; k++) {
        int g = g4 + 4 * k;
        float v = (sp[k] - mu) * rstd * ln_g[g * 64 + d] + ln_b[g * 64 + d];
        bufB[g * 64 + d] = v;
    }
    __syncthreads();

    // S4: m[g][o] = sum_d spec_n[g][d] * mlp_w[d][o]
#pragma unroll
    for (int j = 0; j < 16; j++) bufA[tid + j * 256] = mlp_w[tid + j * 256];
    __syncthreads();
    int o = d;
    float m[8];
#pragma unroll
    for (int k = 0; k < 8; k++) m[k] = 0.f;
#pragma unroll
    for (int dd = 0; dd < 64; dd++) {
        float w = bufA[dd * 64 + o];
#pragma unroll
        for (int k = 0; k < 8; k++) m[k] += bufB[(g4 + 4 * k) * 64 + dd] * w;
    }
#pragma unroll
    for (int k = 0; k < 8; k++) bufC[(g4 + 4 * k) * 64 + o] = m[k];
    __syncthreads();

    // S5: t[g][c] = sum_o m[g][o] * W_out[h*64+o][c]
    int c = tid & 127, g2 = tid >> 7;
    float tacc[16];
#pragma unroll
    for (int k = 0; k < 16; k++) tacc[k] = 0.f;
    for (int oc = 0; oc < 2; oc++) {
#pragma unroll
        for (int j = 0; j < 16; j++) {
            int idx = tid + j * 256;
            int r = idx >> 7, c2 = idx & 127;
            bufA[idx] = W_out[((size_t)(h * 64 + oc * 32 + r)) * CC + c2];
        }
        __syncthreads();
#pragma unroll
        for (int i = 0; i < 32; i++) {
            float w = bufA[i * 128 + c];
            int oo = oc * 32 + i;
#pragma unroll
            for (int k = 0; k < 16; k++) tacc[k] += bufC[(g2 + 2 * k) * 64 + oo] * w;
        }
        __syncthreads();
    }
    size_t tb = (((size_t)b * HH + h) * GG) * CC;
#pragma unroll
    for (int k = 0; k < 16; k++) g_t[tb + (size_t)(g2 + 2 * k) * CC + c] = tacc[k];
}

// ============================================================
// kC: decode: out[b,n,c] = b_out[c] + sum_{h,g} t[b,h,g,c]*inv_out[h,n,g]
// grid (NN/128, BB), 256 threads. CTA tile: 128 n x 128 c.
// Per thread: 8 n x 8 c, 32 FFMA2 per (h,g) k-step.
// ============================================================
__global__ __launch_bounds__(256, 2) void kC(const float* __restrict__ inv_out,
                                             const float* __restrict__ b_out,
                                             float* __restrict__ out) {
    int nt = blockIdx.x, b = blockIdx.y;
    __shared__ float ts[32 * 128];    // 16 KB: [g][c]
    __shared__ float ivs[128 * 32];   // 16 KB: [n][g]
    int tid = threadIdx.x;
    int tx = tid & 15, ty = tid >> 4;
    int c0 = tx * 4;
    int r0 = ty * 8;
    int nbase = nt * 128;

    u64 acc[8][4];
#pragma unroll
    for (int i = 0; i < 8; i++)
#pragma unroll
        for (int j = 0; j < 4; j++) acc[i][j] = 0ull;

    for (int h = 0; h < HH; h++) {
        const float4* tsrc = (const float4*)(g_t + (((size_t)b * HH + h) * GG) * CC);
        float4* td = (float4*)ts;
#pragma unroll
        for (int j = 0; j < 4; j++) td[tid + j * 256] = tsrc[tid + j * 256];
        const float4* isrc = (const float4*)(inv_out + ((size_t)h * NN + nbase) * GG);
        float4* id = (float4*)ivs;
#pragma unroll
        for (int j = 0; j < 4; j++) id[tid + j * 256] = isrc[tid + j * 256];
        __syncthreads();

#pragma unroll 2
        for (int g = 0; g < 32; g++) {
            u64 a[8];
#pragma unroll
            for (int i = 0; i < 8; i++) { float v = ivs[(r0 + i) * 32 + g]; a[i] = pack2(v, v); }
            const float* tr = ts + g * 128 + c0;
            ulonglong2 p0 = *(const ulonglong2*)(tr);
            ulonglong2 p1 = *(const ulonglong2*)(tr + 64);
#pragma unroll
            for (int i = 0; i < 8; i++) {
                ffma2(acc[i][0], a[i], p0.x);
                ffma2(acc[i][1], a[i], p0.y);
                ffma2(acc[i][2], a[i], p1.x);
                ffma2(acc[i][3], a[i], p1.y);
            }
        }
        __syncthreads();
    }

    // epilogue: add bias, store
    float4 bo0 = *(const float4*)(b_out + c0);
    float4 bo1 = *(const float4*)(b_out + c0 + 64);
#pragma unroll
    for (int i = 0; i < 8; i++) {
        int n = nbase + r0 + i;
        float* orow = out + ((size_t)b * NN + n) * CC;
        float f0, f1, f2, f3;
        unpack2(acc[i][0], f0, f1); unpack2(acc[i][1], f2, f3);
        float4 v0; v0.x = f0 + bo0.x; v0.y = f1 + bo0.y; v0.z = f2 + bo0.z; v0.w = f3 + bo0.w;
        *(float4*)(orow + c0) = v0;
        unpack2(acc[i][2], f0, f1); unpack2(acc[i][3], f2, f3);
        float4 v1; v1.x = f0 + bo1.x; v1.y = f1 + bo1.y; v1.z = f2 + bo1.z; v1.w = f3 + bo1.w;
        *(float4*)(orow + c0 + 64) = v1;
    }
}

// ============================================================
extern "C" void kernel_launch(void* const* d_in, const int* in_sizes, int n_in,
                              void* d_out, int out_size) {
    const float* x      = (const float*)d_in[0];
    const float* W_in   = (const float*)d_in[1];
    const float* b_in   = (const float*)d_in[2];
    const float* mlp_w  = (const float*)d_in[3];
    const float* ln_g   = (const float*)d_in[4];
    const float* ln_b   = (const float*)d_in[5];
    const float* W_out  = (const float*)d_in[6];
    const float* b_out  = (const float*)d_in[7];
    const float* inv_in = (const float*)d_in[8];
    const float* inv_out= (const float*)d_in[9];
    float* out = (float*)d_out;

    kS<<<dim3(HH, 16), 256>>>(inv_in);
    kA<<<dim3(SS, HH / 4, BB), 256>>>(x, inv_in);
    kR<<<256, 256>>>();
    kB<<<dim3(HH, BB), 256>>>(W_in, b_in, mlp_w, ln_g, ln_b, W_out);
    kC<<<dim3(NN / 128, BB), 256>>>(inv_out, b_out, out);
}

// round 4
// speedup vs baseline: 2.5966x; 1.8664x over previous
#include <cuda_runtime.h>
#include <cuda_bf16.h>
#include <cstdint>

// Problem constants
#define BB  8
#define NN  8192
#define CC  128
#define HH  8
#define DHH 64
#define GG  32
#define SS  16              // K-splits for encode phase
typedef unsigned long long u64;
typedef __nv_bfloat16 bf16;

// -------- global scratch (no allocation allowed) --------
__device__ bf16  g_xh [(size_t)BB*NN*CC];    // x hi  [b][n][c]
__device__ bf16  g_xl [(size_t)BB*NN*CC];    // x lo
__device__ bf16  g_Ath[(size_t)256*NN];      // inv_in^T hi [hg][n]
__device__ bf16  g_Atl[(size_t)256*NN];
__device__ bf16  g_Aoh[(size_t)NN*256];      // inv_out hi [n][hg]
__device__ bf16  g_Aol[(size_t)NN*256];
__device__ bf16  g_th [(size_t)BB*256*CC];   // middle out hi [b][hg][c]
__device__ bf16  g_tl [(size_t)BB*256*CC];
__device__ float g_Yp [(size_t)SS*BB*256*CC];// encode fp32 partials
__device__ float g_Y  [(size_t)BB*256*CC];
__device__ float g_sinp[16*HH*GG];

// -------- small helpers --------
__device__ __forceinline__ uint32_t smem_u32(const void* p) {
    uint32_t a;
    asm("{ .reg .u64 t; cvta.to.shared.u64 t, %1; cvt.u32.u64 %0, t; }" : "=r"(a) : "l"(p));
    return a;
}
__device__ __forceinline__ void sbf(float v, bf16& h, bf16& l) {
    h = __float2bfloat16(v);
    l = __float2bfloat16(v - __bfloat162float(h));
}
__device__ __forceinline__ uint32_t bp(bf16 a, bf16 b) {
    return (uint32_t)__bfloat16_as_ushort(a) | ((uint32_t)__bfloat16_as_ushort(b) << 16);
}
__device__ __forceinline__ void cpa16(uint32_t dst, const void* src) {
    asm volatile("cp.async.cg.shared.global [%0], [%1], 16;" :: "r"(dst), "l"(src));
}
__device__ __forceinline__ void cpcommit() { asm volatile("cp.async.commit_group;" ::: "memory"); }
template<int N> __device__ __forceinline__ void cpwait() {
    asm volatile("cp.async.wait_group %0;" :: "n"(N) : "memory");
}
__device__ __forceinline__ void ldm4(uint32_t* r, uint32_t a) {
    asm volatile("ldmatrix.sync.aligned.m8n8.x4.shared.b16 {%0,%1,%2,%3}, [%4];"
                 : "=r"(r[0]), "=r"(r[1]), "=r"(r[2]), "=r"(r[3]) : "r"(a));
}
__device__ __forceinline__ void ldm4t(uint32_t* r, uint32_t a) {
    asm volatile("ldmatrix.sync.aligned.m8n8.x4.trans.shared.b16 {%0,%1,%2,%3}, [%4];"
                 : "=r"(r[0]), "=r"(r[1]), "=r"(r[2]), "=r"(r[3]) : "r"(a));
}
__device__ __forceinline__ void mma16816(float* d, const uint32_t* a, const uint32_t* b) {
    asm volatile(
        "mma.sync.aligned.m16n8k16.row.col.f32.bf16.bf16.f32 "
        "{%0,%1,%2,%3}, {%4,%5,%6,%7}, {%8,%9}, {%0,%1,%2,%3};"
        : "+f"(d[0]), "+f"(d[1]), "+f"(d[2]), "+f"(d[3])
        : "r"(a[0]), "r"(a[1]), "r"(a[2]), "r"(a[3]), "r"(b[0]), "r"(b[1]));
}

// smem stage layout (bytes)
#define OFFAH 0
#define OFFAL 8192
#define OFFBH 16384
#define OFFBL 24576
#define STG   32768
#define SMEM_DYN (2*STG)

// A tile: 128 rows x 32 k bf16, row=64B=4 chunks, phys chunk = kc ^ ((r>>1)&3)
__device__ __forceinline__ uint32_t offA(int r, int kc) {
    return (uint32_t)(r * 64 + ((kc ^ ((r >> 1) & 3)) << 4));
}
// B tile: 32 k rows x 128 n bf16, row=256B=16 chunks, phys chunk = nc ^ (r&7)
__device__ __forceinline__ uint32_t offB(int r, int nc) {
    return (uint32_t)(r * 256 + ((nc ^ (r & 7)) << 4));
}

// fill one stage: A (hi/lo) and B (hi/lo). 8 cp.async per thread.
__device__ __forceinline__ void fill_stage(uint32_t sma,
        const bf16* Ah, const bf16* Al, size_t sA,
        const bf16* Bh, const bf16* Bl, int tid) {
#pragma unroll
    for (int i = 0; i < 2; i++) {
        int idx = tid + i * 256;           // 0..511
        int r = idx >> 2, kc = idx & 3;
        uint32_t o = offA(r, kc);
        const bf16* sa = Ah + (size_t)r * sA + kc * 8;
        const bf16* sl = Al + (size_t)r * sA + kc * 8;
        cpa16(sma + OFFAH + o, sa);
        cpa16(sma + OFFAL + o, sl);
    }
#pragma unroll
    for (int i = 0; i < 2; i++) {
        int idx = tid + i * 256;
        int r = idx >> 4, nc = idx & 15;
        uint32_t o = offB(r, nc);
        cpa16(sma + OFFBH + o, Bh + r * CC + nc * 8);
        cpa16(sma + OFFBL + o, Bl + r * CC + nc * 8);
    }
}

// compute one BK=32 stage: 2 k16 halves, 3-term split
__device__ __forceinline__ void compute_stage(uint32_t sma, int wm, int wn, int lane,
                                              float acc[2][8][4]) {
#pragma unroll
    for (int kk = 0; kk < 2; kk++) {
        uint32_t ah[2][4], al[2][4];
        int arow = wm * 32 + (lane & 15);
        int akc = kk * 2 + (lane >> 4);
#pragma unroll
        for (int mt = 0; mt < 2; mt++) {
            int r = arow + mt * 16;
            uint32_t o = offA(r, akc);
            ldm4(ah[mt], sma + OFFAH + o);
            ldm4(al[mt], sma + OFFAL + o);
        }
        int brow = kk * 16 + (lane & 15);
#pragma unroll
        for (int ng = 0; ng < 4; ng++) {
            uint32_t bh[4], bl[4];
            int nc = wn * 8 + ng * 2 + (lane >> 4);
            uint32_t o = offB(brow, nc);
            ldm4t(bh, sma + OFFBH + o);
            ldm4t(bl, sma + OFFBL + o);
#pragma unroll
            for (int mt = 0; mt < 2; mt++) {
#pragma unroll
                for (int s2 = 0; s2 < 2; s2++) {
                    float* d = acc[mt][ng * 2 + s2];
                    mma16816(d, ah[mt], bh + s2 * 2);
                    mma16816(d, ah[mt], bl + s2 * 2);
                    mma16816(d, al[mt], bh + s2 * 2);
                }
            }
        }
    }
}

// ============================================================
// kPx: x -> bf16 hi/lo
// ============================================================
__global__ __launch_bounds__(256) void kPx(const float* __restrict__ x) {
    const float4* src = (const float4*)x;
#pragma unroll
    for (int i = 0; i < 4; i++) {
        size_t idx = (size_t)blockIdx.x * 1024 + i * 256 + threadIdx.x;  // float4 idx
        float4 v = src[idx];
        bf16 hx, lx, hy, ly, hz, lz, hw, lw;
        sbf(v.x, hx, lx); sbf(v.y, hy, ly); sbf(v.z, hz, lz); sbf(v.w, hw, lw);
        uint2 ph; ph.x = bp(hx, hy); ph.y = bp(hz, hw);
        uint2 pl; pl.x = bp(lx, ly); pl.y = bp(lz, lw);
        ((uint2*)g_xh)[idx] = ph;
        ((uint2*)g_xl)[idx] = pl;
    }
}

// ============================================================
// kPin: inv_in [h][n][g] -> At[hg][n] hi/lo. grid (8, 64), 256 thr.
// ============================================================
__global__ __launch_bounds__(256) void kPin(const float* __restrict__ inv_in) {
    __shared__ float s[128][33];
    int h = blockIdx.x, nb = blockIdx.y * 128, tid = threadIdx.x;
    const float4* src = (const float4*)(inv_in + ((size_t)h * NN + nb) * GG);
#pragma unroll
    for (int i = 0; i < 4; i++) {
        int f = tid + i * 256;
        int n = f >> 3, q = f & 7;
        float4 v = src[f];
        s[n][q * 4] = v.x; s[n][q * 4 + 1] = v.y; s[n][q * 4 + 2] = v.z; s[n][q * 4 + 3] = v.w;
    }
    __syncthreads();
    int g = tid >> 3, j = tid & 7;
    uint4 uh[2], ul[2];
    bf16* ph = (bf16*)uh;
    bf16* pl = (bf16*)ul;
#pragma unroll
    for (int i = 0; i < 16; i++) sbf(s[j * 16 + i][g], ph[i], pl[i]);
    size_t off = ((size_t)(h * 32 + g)) * NN + nb + j * 16;
    *(uint4*)(g_Ath + off) = uh[0]; *(uint4*)(g_Ath + off + 8) = uh[1];
    *(uint4*)(g_Atl + off) = ul[0]; *(uint4*)(g_Atl + off + 8) = ul[1];
}

// ============================================================
// kPout: inv_out [h][n][g] -> Ao[n][hg] hi/lo. grid (64), 256 thr.
// ============================================================
__global__ __launch_bounds__(256) void kPout(const float* __restrict__ inv_out) {
    __shared__ float s[128][33];
    int nb = blockIdx.x * 128, tid = threadIdx.x;
    for (int h = 0; h < 8; h++) {
        const float4* src = (const float4*)(inv_out + ((size_t)h * NN + nb) * GG);
#pragma unroll
        for (int i = 0; i < 4; i++) {
            int f = tid + i * 256;
            int n = f >> 3, q = f & 7;
            float4 v = src[f];
            s[n][q * 4] = v.x; s[n][q * 4 + 1] = v.y; s[n][q * 4 + 2] = v.z; s[n][q * 4 + 3] = v.w;
        }
        __syncthreads();
        int n = tid >> 1, half = tid & 1;
        uint4 uh[2], ul[2];
        bf16* ph = (bf16*)uh;
        bf16* pl = (bf16*)ul;
#pragma unroll
        for (int i = 0; i < 16; i++) sbf(s[n][half * 16 + i], ph[i], pl[i]);
        size_t off = ((size_t)(nb + n)) * 256 + h * 32 + half * 16;
        *(uint4*)(g_Aoh + off) = uh[0]; *(uint4*)(g_Aoh + off + 8) = uh[1];
        *(uint4*)(g_Aol + off) = ul[0]; *(uint4*)(g_Aol + off + 8) = ul[1];
        __syncthreads();
    }
}

// ============================================================
// kS: chunk partials of s_in[h,g] = sum_n inv_in[h,n,g]
// ============================================================
__global__ __launch_bounds__(256) void kS(const float* __restrict__ inv_in) {
    int h = blockIdx.x, ch = blockIdx.y, tid = threadIdx.x;
    int lane = tid & 31, warp = tid >> 5;
    float acc[32];
#pragma unroll
    for (int g = 0; g < 32; g++) acc[g] = 0.f;
    int n0 = ch * 512;
    for (int n = n0 + tid; n < n0 + 512; n += 256) {
        const float4* r = (const float4*)(inv_in + ((size_t)h * NN + n) * GG);
#pragma unroll
        for (int q = 0; q < 8; q++) {
            float4 v = r[q];
            acc[4*q+0] += v.x; acc[4*q+1] += v.y; acc[4*q+2] += v.z; acc[4*q+3] += v.w;
        }
    }
#pragma unroll
    for (int off = 16; off; off >>= 1)
#pragma unroll
        for (int g = 0; g < 32; g++) acc[g] += __shfl_xor_sync(0xffffffffu, acc[g], off);
    __shared__ float wred[8][32];
    if (lane == 0)
#pragma unroll
        for (int g = 0; g < 32; g++) wred[warp][g] = acc[g];
    __syncthreads();
    if (tid < 32) {
        float s = 0.f;
#pragma unroll
        for (int w = 0; w < 8; w++) s += wred[w][tid];
        g_sinp[ch * (HH * GG) + h * 32 + tid] = s;
    }
}

// ============================================================
// kE: encode GEMM partials. grid (2, SS, BB), 256 thr.
//   C[mhalf*128 + m][c] over K=512 (split s) -> g_Yp fp32
// ============================================================
extern __shared__ char dsm[];
__global__ __launch_bounds__(256, 2) void kE() {
    int tid = threadIdx.x, lane = tid & 31, wid = tid >> 5;
    int wm = wid & 3, wn = wid >> 2;
    int mhalf = blockIdx.x, s = blockIdx.y, b = blockIdx.z;

    const bf16* Ah = g_Ath + (size_t)(mhalf * 128) * NN + s * 512;
    const bf16* Al = g_Atl + (size_t)(mhalf * 128) * NN + s * 512;
    const bf16* Bh = g_xh + ((size_t)b * NN + s * 512) * CC;
    const bf16* Bl = g_xl + ((size_t)b * NN + s * 512) * CC;

    float acc[2][8][4];
#pragma unroll
    for (int i = 0; i < 2; i++)
#pragma unroll
        for (int j = 0; j < 8; j++)
#pragma unroll
            for (int k = 0; k < 4; k++) acc[i][j][k] = 0.f;

    uint32_t sma = smem_u32(dsm);
    const int NST = 16;
    fill_stage(sma, Ah, Al, NN, Bh, Bl, tid);
    cpcommit();
#pragma unroll 1
    for (int st = 0; st < NST; st++) {
        if (st + 1 < NST) {
            fill_stage(sma + ((st + 1) & 1) * STG,
                       Ah + (st + 1) * 32, Al + (st + 1) * 32, NN,
                       Bh + (size_t)(st + 1) * 32 * CC, Bl + (size_t)(st + 1) * 32 * CC, tid);
            cpcommit();
            cpwait<1>();
        } else {
            cpwait<0>();
        }
        __syncthreads();
        compute_stage(sma + (st & 1) * STG, wm, wn, lane, acc);
        __syncthreads();
    }

    int g = lane >> 2, t4 = lane & 3;
    size_t base = (((size_t)s * BB + b) * 256 + mhalf * 128);
#pragma unroll
    for (int mt = 0; mt < 2; mt++) {
#pragma unroll
        for (int nt = 0; nt < 8; nt++) {
            int rr = wm * 32 + mt * 16 + g;
            int cc = wn * 64 + nt * 8 + t4 * 2;
            float2 v0; v0.x = acc[mt][nt][0]; v0.y = acc[mt][nt][1];
            *(float2*)(g_Yp + (base + rr) * CC + cc) = v0;
            float2 v1; v1.x = acc[mt][nt][2]; v1.y = acc[mt][nt][3];
            *(float2*)(g_Yp + (base + rr + 8) * CC + cc) = v1;
        }
    }
}

// ============================================================
// kR: reduce partials over SS splits
// ============================================================
__global__ __launch_bounds__(256) void kR() {
    int i4 = blockIdx.x * 256 + threadIdx.x;   // 0..65535
    const float4* p = (const float4*)g_Yp;
    float4 s = make_float4(0.f, 0.f, 0.f, 0.f);
    const size_t stride4 = (size_t)BB * 256 * CC / 4;
#pragma unroll
    for (int ss = 0; ss < SS; ss++) {
        float4 v = p[(size_t)ss * stride4 + i4];
        s.x += v.x; s.y += v.y; s.z += v.z; s.w += v.w;
    }
    ((float4*)g_Y)[i4] = s;
}

// ============================================================
// kB: middle per (b,h): spec = Y@W_in_h + bias; LN; @mlp_w; @W_out_h
//     -> g_th/g_tl bf16. grid (HH, BB), 256 thr.
// ============================================================
__global__ __launch_bounds__(256) void kB(const float* __restrict__ W_in,
                                          const float* __restrict__ b_in,
                                          const float* __restrict__ mlp_w,
                                          const float* __restrict__ ln_g,
                                          const float* __restrict__ ln_b,
                                          const float* __restrict__ W_out) {
    int h = blockIdx.x, b = blockIdx.y;
    __shared__ float bufA[4096];
    __shared__ float bufB[2048];
    __shared__ float bufC[2048];
    __shared__ float red[16];
    int tid = threadIdx.x;

#pragma unroll
    for (int k = 0; k < 16; k++) {
        int idx = tid + k * 256;
        bufA[idx] = g_Y[((size_t)(b * HH + h)) * 4096 + idx];
    }
    __syncthreads();

    int d = tid & 63, g4 = tid >> 6;
    float sp[8];
#pragma unroll
    for (int k = 0; k < 8; k++) sp[k] = 0.f;
    for (int cc = 0; cc < 4; cc++) {
#pragma unroll
        for (int j = 0; j < 8; j++) {
            int idx = tid + j * 256;
            int r = idx >> 6, dd = idx & 63;
            bufB[idx] = W_in[((size_t)(cc * 32 + r)) * (HH * DHH) + h * 64 + dd];
        }
        __syncthreads();
#pragma unroll
        for (int i = 0; i < 32; i++) {
            float w = bufB[i * 64 + d];
            int c = cc * 32 + i;
#pragma unroll
            for (int k = 0; k < 8; k++) sp[k] += bufA[(g4 + 4 * k) * 128 + c] * w;
        }
        __syncthreads();
    }

    float bv = b_in[h * 64 + d];
#pragma unroll
    for (int k = 0; k < 8; k++) {
        int g = g4 + 4 * k;
        float sv = 0.f;
#pragma unroll
        for (int ch = 0; ch < 16; ch++) sv += g_sinp[ch * (HH * GG) + h * 32 + g];
        sp[k] += bv * sv;
    }

    float lsum = 0.f, lsq = 0.f;
#pragma unroll
    for (int k = 0; k < 8; k++) { lsum += sp[k]; lsq += sp[k] * sp[k]; }
#pragma unroll
    for (int off = 16; off; off >>= 1) {
        lsum += __shfl_xor_sync(0xffffffffu, lsum, off);
        lsq  += __shfl_xor_sync(0xffffffffu, lsq,  off);
    }
    int warp = tid >> 5, lane = tid & 31;
    if (lane == 0) { red[warp] = lsum; red[8 + warp] = lsq; }
    __syncthreads();
    float tsum = 0.f, tsq = 0.f;
#pragma unroll
    for (int w = 0; w < 8; w++) { tsum += red[w]; tsq += red[8 + w]; }
    float mu = tsum * (1.f / 2048.f);
    float var = tsq * (1.f / 2048.f) - mu * mu;
    float rstd = rsqrtf(var + 1e-5f);
    __syncthreads();
#pragma unroll
    for (int k = 0; k < 8; k++) {
        int g = g4 + 4 * k;
        float v = (sp[k] - mu) * rstd * ln_g[g * 64 + d] + ln_b[g * 64 + d];
        bufB[g * 64 + d] = v;
    }
    __syncthreads();

#pragma unroll
    for (int j = 0; j < 16; j++) bufA[tid + j * 256] = mlp_w[tid + j * 256];
    __syncthreads();
    int o = d;
    float m[8];
#pragma unroll
    for (int k = 0; k < 8; k++) m[k] = 0.f;
#pragma unroll
    for (int dd = 0; dd < 64; dd++) {
        float w = bufA[dd * 64 + o];
#pragma unroll
        for (int k = 0; k < 8; k++) m[k] += bufB[(g4 + 4 * k) * 64 + dd] * w;
    }
#pragma unroll
    for (int k = 0; k < 8; k++) bufC[(g4 + 4 * k) * 64 + o] = m[k];
    __syncthreads();

    int c = tid & 127, g2 = tid >> 7;
    float tacc[16];
#pragma unroll
    for (int k = 0; k < 16; k++) tacc[k] = 0.f;
    for (int oc = 0; oc < 2; oc++) {
#pragma unroll
        for (int j = 0; j < 16; j++) {
            int idx = tid + j * 256;
            int r = idx >> 7, c2 = idx & 127;
            bufA[idx] = W_out[((size_t)(h * 64 + oc * 32 + r)) * CC + c2];
        }
        __syncthreads();
#pragma unroll
        for (int i = 0; i < 32; i++) {
            float w = bufA[i * 128 + c];
            int oo = oc * 32 + i;
#pragma unroll
            for (int k = 0; k < 16; k++) tacc[k] += bufC[(g2 + 2 * k) * 64 + oo] * w;
        }
        __syncthreads();
    }
    size_t tb = ((size_t)b * 256 + h * 32) * CC;
#pragma unroll
    for (int k = 0; k < 16; k++) {
        bf16 th, tl;
        sbf(tacc[k], th, tl);
        size_t off = tb + (size_t)(g2 + 2 * k) * CC + c;
        g_th[off] = th;
        g_tl[off] = tl;
    }
}

// ============================================================
// kD: decode GEMM: out[b][nt*128+m][c] = bias + A[n][hg] * B[hg][c], K=256.
// grid (64, BB), 256 thr.
// ============================================================
__global__ __launch_bounds__(256, 2) void kD(const float* __restrict__ b_out,
                                             float* __restrict__ out) {
    int tid = threadIdx.x, lane = tid & 31, wid = tid >> 5;
    int wm = wid & 3, wn = wid >> 2;
    int ntb = blockIdx.x, b = blockIdx.y;

    const bf16* Ah = g_Aoh + (size_t)(ntb * 128) * 256;
    const bf16* Al = g_Aol + (size_t)(ntb * 128) * 256;
    const bf16* Bh = g_th + (size_t)b * 256 * CC;
    const bf16* Bl = g_tl + (size_t)b * 256 * CC;

    float acc[2][8][4];
#pragma unroll
    for (int i = 0; i < 2; i++)
#pragma unroll
        for (int j = 0; j < 8; j++)
#pragma unroll
            for (int k = 0; k < 4; k++) acc[i][j][k] = 0.f;

    uint32_t sma = smem_u32(dsm);
    const int NST = 8;
    fill_stage(sma, Ah, Al, 256, Bh, Bl, tid);
    cpcommit();
#pragma unroll 1
    for (int st = 0; st < NST; st++) {
        if (st + 1 < NST) {
            fill_stage(sma + ((st + 1) & 1) * STG,
                       Ah + (st + 1) * 32, Al + (st + 1) * 32, 256,
                       Bh + (size_t)(st + 1) * 32 * CC, Bl + (size_t)(st + 1) * 32 * CC, tid);
            cpcommit();
            cpwait<1>();
        } else {
            cpwait<0>();
        }
        __syncthreads();
        compute_stage(sma + (st & 1) * STG, wm, wn, lane, acc);
        __syncthreads();
    }

    int g = lane >> 2, t4 = lane & 3;
#pragma unroll
    for (int mt = 0; mt < 2; mt++) {
#pragma unroll
        for (int nt = 0; nt < 8; nt++) {
            int rr = wm * 32 + mt * 16 + g;
            int cc = wn * 64 + nt * 8 + t4 * 2;
            float2 bo = *(const float2*)(b_out + cc);
            size_t row0 = ((size_t)b * NN + ntb * 128 + rr) * CC;
            float2 v0; v0.x = acc[mt][nt][0] + bo.x; v0.y = acc[mt][nt][1] + bo.y;
            *(float2*)(out + row0 + cc) = v0;
            float2 v1; v1.x = acc[mt][nt][2] + bo.x; v1.y = acc[mt][nt][3] + bo.y;
            *(float2*)(out + row0 + 8 * CC + cc) = v1;
        }
    }
}

// ============================================================
extern "C" void kernel_launch(void* const* d_in, const int* in_sizes, int n_in,
                              void* d_out, int out_size) {
    const float* x      = (const float*)d_in[0];
    const float* W_in   = (const float*)d_in[1];
    const float* b_in   = (const float*)d_in[2];
    const float* mlp_w  = (const float*)d_in[3];
    const float* ln_g   = (const float*)d_in[4];
    const float* ln_b   = (const float*)d_in[5];
    const float* W_out  = (const float*)d_in[6];
    const float* b_out  = (const float*)d_in[7];
    const float* inv_in = (const float*)d_in[8];
    const float* inv_out= (const float*)d_in[9];
    float* out = (float*)d_out;

    cudaFuncSetAttribute(kE, cudaFuncAttributeMaxDynamicSharedMemorySize, SMEM_DYN);
    cudaFuncSetAttribute(kD, cudaFuncAttributeMaxDynamicSharedMemorySize, SMEM_DYN);

    kPx<<<2048, 256>>>(x);
    kPin<<<dim3(8, 64), 256>>>(inv_in);
    kPout<<<64, 256>>>(inv_out);
    kS<<<dim3(HH, 16), 256>>>(inv_in);
    kE<<<dim3(2, SS, BB), 256, SMEM_DYN>>>();
    kR<<<256, 256>>>();
    kB<<<dim3(HH, BB), 256>>>(W_in, b_in, mlp_w, ln_g, ln_b, W_out);
    kD<<<dim3(64, BB), 256, SMEM_DYN>>>(b_out, out);
}

// round 5
// speedup vs baseline: 2.6958x; 1.0382x over previous
#include <cuda_runtime.h>
#include <cuda_bf16.h>
#include <cstdint>

// Problem constants
#define BB  8
#define NN  8192
#define CC  128
#define HH  8
#define DHH 64
#define GG  32
#define SS  16              // K-splits for encode phase
typedef unsigned long long u64;
typedef __nv_bfloat16 bf16;

// -------- global scratch (no allocation allowed) --------
__device__ bf16  g_xh [(size_t)BB*NN*CC];    // x hi  [b][n][c]
__device__ bf16  g_xl [(size_t)BB*NN*CC];    // x lo
__device__ bf16  g_Ath[(size_t)256*NN];      // inv_in^T hi [hg][n]
__device__ bf16  g_Atl[(size_t)256*NN];
__device__ bf16  g_Aoh[(size_t)NN*256];      // inv_out hi [n][hg]
__device__ bf16  g_Aol[(size_t)NN*256];
__device__ bf16  g_th [(size_t)BB*256*CC];   // middle out hi [b][hg][c]
__device__ bf16  g_tl [(size_t)BB*256*CC];
__device__ float g_Yp [(size_t)SS*BB*256*CC];// encode fp32 partials
__device__ float g_Y  [(size_t)BB*256*CC];
__device__ float g_sinp[64*HH*GG];           // 64-chunk partials of sum_n inv_in

// -------- small helpers --------
__device__ __forceinline__ uint32_t smem_u32(const void* p) {
    uint32_t a;
    asm("{ .reg .u64 t; cvta.to.shared.u64 t, %1; cvt.u32.u64 %0, t; }" : "=r"(a) : "l"(p));
    return a;
}
__device__ __forceinline__ void sbf(float v, bf16& h, bf16& l) {
    h = __float2bfloat16(v);
    l = __float2bfloat16(v - __bfloat162float(h));
}
__device__ __forceinline__ uint32_t bp(bf16 a, bf16 b) {
    return (uint32_t)__bfloat16_as_ushort(a) | ((uint32_t)__bfloat16_as_ushort(b) << 16);
}
__device__ __forceinline__ void cpa16(uint32_t dst, const void* src) {
    asm volatile("cp.async.cg.shared.global [%0], [%1], 16;" :: "r"(dst), "l"(src));
}
__device__ __forceinline__ void cpcommit() { asm volatile("cp.async.commit_group;" ::: "memory"); }
template<int N> __device__ __forceinline__ void cpwait() {
    asm volatile("cp.async.wait_group %0;" :: "n"(N) : "memory");
}
__device__ __forceinline__ void ldm4(uint32_t* r, uint32_t a) {
    asm volatile("ldmatrix.sync.aligned.m8n8.x4.shared.b16 {%0,%1,%2,%3}, [%4];"
                 : "=r"(r[0]), "=r"(r[1]), "=r"(r[2]), "=r"(r[3]) : "r"(a));
}
__device__ __forceinline__ void ldm4t(uint32_t* r, uint32_t a) {
    asm volatile("ldmatrix.sync.aligned.m8n8.x4.trans.shared.b16 {%0,%1,%2,%3}, [%4];"
                 : "=r"(r[0]), "=r"(r[1]), "=r"(r[2]), "=r"(r[3]) : "r"(a));
}
__device__ __forceinline__ void mma16816(float* d, const uint32_t* a, const uint32_t* b) {
    asm volatile(
        "mma.sync.aligned.m16n8k16.row.col.f32.bf16.bf16.f32 "
        "{%0,%1,%2,%3}, {%4,%5,%6,%7}, {%8,%9}, {%0,%1,%2,%3};"
        : "+f"(d[0]), "+f"(d[1]), "+f"(d[2]), "+f"(d[3])
        : "r"(a[0]), "r"(a[1]), "r"(a[2]), "r"(a[3]), "r"(b[0]), "r"(b[1]));
}

// smem stage layout (bytes)
#define OFFAH 0
#define OFFAL 8192
#define OFFBH 16384
#define OFFBL 24576
#define STG   32768
#define SMEM_DYN (3*STG)

// A tile: 128 rows x 32 k bf16, row=64B=4 chunks, phys chunk = kc ^ ((r>>1)&3)
__device__ __forceinline__ uint32_t offA(int r, int kc) {
    return (uint32_t)(r * 64 + ((kc ^ ((r >> 1) & 3)) << 4));
}
// B tile: 32 k rows x 128 n bf16, row=256B=16 chunks, phys chunk = nc ^ (r&7)
__device__ __forceinline__ uint32_t offB(int r, int nc) {
    return (uint32_t)(r * 256 + ((nc ^ (r & 7)) << 4));
}

// fill one stage: A (hi/lo) and B (hi/lo). 8 cp.async per thread.
__device__ __forceinline__ void fill_stage(uint32_t sma,
        const bf16* Ah, const bf16* Al, size_t sA,
        const bf16* Bh, const bf16* Bl, int tid) {
#pragma unroll
    for (int i = 0; i < 2; i++) {
        int idx = tid + i * 256;           // 0..511
        int r = idx >> 2, kc = idx & 3;
        uint32_t o = offA(r, kc);
        const bf16* sa = Ah + (size_t)r * sA + kc * 8;
        const bf16* sl = Al + (size_t)r * sA + kc * 8;
        cpa16(sma + OFFAH + o, sa);
        cpa16(sma + OFFAL + o, sl);
    }
#pragma unroll
    for (int i = 0; i < 2; i++) {
        int idx = tid + i * 256;
        int r = idx >> 4, nc = idx & 15;
        uint32_t o = offB(r, nc);
        cpa16(sma + OFFBH + o, Bh + r * CC + nc * 8);
        cpa16(sma + OFFBL + o, Bl + r * CC + nc * 8);
    }
}

// compute one BK=32 stage: 2 k16 halves, 3-term split
__device__ __forceinline__ void compute_stage(uint32_t sma, int wm, int wn, int lane,
                                              float acc[2][8][4]) {
#pragma unroll
    for (int kk = 0; kk < 2; kk++) {
        uint32_t ah[2][4], al[2][4];
        int arow = wm * 32 + (lane & 15);
        int akc = kk * 2 + (lane >> 4);
#pragma unroll
        for (int mt = 0; mt < 2; mt++) {
            int r = arow + mt * 16;
            uint32_t o = offA(r, akc);
            ldm4(ah[mt], sma + OFFAH + o);
            ldm4(al[mt], sma + OFFAL + o);
        }
        int brow = kk * 16 + (lane & 15);
#pragma unroll
        for (int ng = 0; ng < 4; ng++) {
            uint32_t bh[4], bl[4];
            int nc = wn * 8 + ng * 2 + (lane >> 4);
            uint32_t o = offB(brow, nc);
            ldm4t(bh, sma + OFFBH + o);
            ldm4t(bl, sma + OFFBL + o);
#pragma unroll
            for (int mt = 0; mt < 2; mt++) {
#pragma unroll
                for (int s2 = 0; s2 < 2; s2++) {
                    float* d = acc[mt][ng * 2 + s2];
                    mma16816(d, ah[mt], bh + s2 * 2);
                    mma16816(d, ah[mt], bl + s2 * 2);
                    mma16816(d, al[mt], bh + s2 * 2);
                }
            }
        }
    }
}

// ============================================================
// kPx: x -> bf16 hi/lo
// ============================================================
__global__ __launch_bounds__(256) void kPx(const float* __restrict__ x) {
    const float4* src = (const float4*)x;
#pragma unroll
    for (int i = 0; i < 4; i++) {
        size_t idx = (size_t)blockIdx.x * 1024 + i * 256 + threadIdx.x;  // float4 idx
        float4 v = src[idx];
        bf16 hx, lx, hy, ly, hz, lz, hw, lw;
        sbf(v.x, hx, lx); sbf(v.y, hy, ly); sbf(v.z, hz, lz); sbf(v.w, hw, lw);
        uint2 ph; ph.x = bp(hx, hy); ph.y = bp(hz, hw);
        uint2 pl; pl.x = bp(lx, ly); pl.y = bp(lz, lw);
        ((uint2*)g_xh)[idx] = ph;
        ((uint2*)g_xl)[idx] = pl;
    }
}

// ============================================================
// kPin: inv_in [h][n][g] -> At[hg][n] hi/lo  +  chunk sums of inv_in.
// grid (8, 64), 256 thr.
// ============================================================
__global__ __launch_bounds__(256) void kPin(const float* __restrict__ inv_in) {
    __shared__ float s[128][33];
    __shared__ float ps[32][9];
    int h = blockIdx.x, nb = blockIdx.y * 128, tid = threadIdx.x;
    const float4* src = (const float4*)(inv_in + ((size_t)h * NN + nb) * GG);
#pragma unroll
    for (int i = 0; i < 4; i++) {
        int f = tid + i * 256;
        int n = f >> 3, q = f & 7;
        float4 v = src[f];
        s[n][q * 4] = v.x; s[n][q * 4 + 1] = v.y; s[n][q * 4 + 2] = v.z; s[n][q * 4 + 3] = v.w;
    }
    __syncthreads();
    int g = tid >> 3, j = tid & 7;
    uint4 uh[2], ul[2];
    bf16* ph = (bf16*)uh;
    bf16* pl = (bf16*)ul;
    float psum = 0.f;
#pragma unroll
    for (int i = 0; i < 16; i++) {
        float v = s[j * 16 + i][g];
        psum += v;
        sbf(v, ph[i], pl[i]);
    }
    size_t off = ((size_t)(h * 32 + g)) * NN + nb + j * 16;
    *(uint4*)(g_Ath + off) = uh[0]; *(uint4*)(g_Ath + off + 8) = uh[1];
    *(uint4*)(g_Atl + off) = ul[0]; *(uint4*)(g_Atl + off + 8) = ul[1];
    ps[g][j] = psum;
    __syncthreads();
    if (tid < 32) {
        float t = 0.f;
#pragma unroll
        for (int jj = 0; jj < 8; jj++) t += ps[tid][jj];
        g_sinp[blockIdx.y * 256 + h * 32 + tid] = t;
    }
}

// ============================================================
// kPout: inv_out [h][n][g] -> Ao[n][hg] hi/lo. grid (64), 256 thr.
// ============================================================
__global__ __launch_bounds__(256) void kPout(const float* __restrict__ inv_out) {
    __shared__ float s[128][33];
    int nb = blockIdx.x * 128, tid = threadIdx.x;
    for (int h = 0; h < 8; h++) {
        const float4* src = (const float4*)(inv_out + ((size_t)h * NN + nb) * GG);
#pragma unroll
        for (int i = 0; i < 4; i++) {
            int f = tid + i * 256;
            int n = f >> 3, q = f & 7;
            float4 v = src[f];
            s[n][q * 4] = v.x; s[n][q * 4 + 1] = v.y; s[n][q * 4 + 2] = v.z; s[n][q * 4 + 3] = v.w;
        }
        __syncthreads();
        int n = tid >> 1, half = tid & 1;
        uint4 uh[2], ul[2];
        bf16* ph = (bf16*)uh;
        bf16* pl = (bf16*)ul;
#pragma unroll
        for (int i = 0; i < 16; i++) sbf(s[n][half * 16 + i], ph[i], pl[i]);
        size_t off = ((size_t)(nb + n)) * 256 + h * 32 + half * 16;
        *(uint4*)(g_Aoh + off) = uh[0]; *(uint4*)(g_Aoh + off + 8) = uh[1];
        *(uint4*)(g_Aol + off) = ul[0]; *(uint4*)(g_Aol + off + 8) = ul[1];
        __syncthreads();
    }
}

// ============================================================
// kE: encode GEMM partials. grid (2, SS, BB), 256 thr, 3-stage ring.
// ============================================================
extern __shared__ char dsm[];
__global__ __launch_bounds__(256, 2) void kE() {
    int tid = threadIdx.x, lane = tid & 31, wid = tid >> 5;
    int wm = wid & 3, wn = wid >> 2;
    int mhalf = blockIdx.x, s = blockIdx.y, b = blockIdx.z;

    const bf16* Ah = g_Ath + (size_t)(mhalf * 128) * NN + s * 512;
    const bf16* Al = g_Atl + (size_t)(mhalf * 128) * NN + s * 512;
    const bf16* Bh = g_xh + ((size_t)b * NN + s * 512) * CC;
    const bf16* Bl = g_xl + ((size_t)b * NN + s * 512) * CC;

    float acc[2][8][4];
#pragma unroll
    for (int i = 0; i < 2; i++)
#pragma unroll
        for (int j = 0; j < 8; j++)
#pragma unroll
            for (int k = 0; k < 4; k++) acc[i][j][k] = 0.f;

    uint32_t sma = smem_u32(dsm);
    const int NST = 16;
    fill_stage(sma, Ah, Al, NN, Bh, Bl, tid);
    cpcommit();
    fill_stage(sma + STG, Ah + 32, Al + 32, NN,
               Bh + (size_t)32 * CC, Bl + (size_t)32 * CC, tid);
    cpcommit();
#pragma unroll 1
    for (int st = 0; st < NST; st++) {
        if (st + 2 < NST) {
            int nb = st + 2;
            fill_stage(sma + (nb % 3) * STG,
                       Ah + nb * 32, Al + nb * 32, NN,
                       Bh + (size_t)nb * 32 * CC, Bl + (size_t)nb * 32 * CC, tid);
            cpcommit();
            cpwait<2>();
        } else {
            cpwait<0>();
        }
        __syncthreads();
        compute_stage(sma + (st % 3) * STG, wm, wn, lane, acc);
        __syncthreads();
    }

    int g = lane >> 2, t4 = lane & 3;
    size_t base = (((size_t)s * BB + b) * 256 + mhalf * 128);
#pragma unroll
    for (int mt = 0; mt < 2; mt++) {
#pragma unroll
        for (int nt = 0; nt < 8; nt++) {
            int rr = wm * 32 + mt * 16 + g;
            int cc = wn * 64 + nt * 8 + t4 * 2;
            float2 v0; v0.x = acc[mt][nt][0]; v0.y = acc[mt][nt][1];
            *(float2*)(g_Yp + (base + rr) * CC + cc) = v0;
            float2 v1; v1.x = acc[mt][nt][2]; v1.y = acc[mt][nt][3];
            *(float2*)(g_Yp + (base + rr + 8) * CC + cc) = v1;
        }
    }
}

// ============================================================
// kR: reduce partials over SS splits
// ============================================================
__global__ __launch_bounds__(256) void kR() {
    int i4 = blockIdx.x * 256 + threadIdx.x;   // 0..65535
    const float4* p = (const float4*)g_Yp;
    float4 s = make_float4(0.f, 0.f, 0.f, 0.f);
    const size_t stride4 = (size_t)BB * 256 * CC / 4;
#pragma unroll
    for (int ss = 0; ss < SS; ss++) {
        float4 v = p[(size_t)ss * stride4 + i4];
        s.x += v.x; s.y += v.y; s.z += v.z; s.w += v.w;
    }
    ((float4*)g_Y)[i4] = s;
}

// ============================================================
// kB: middle per (b,h): spec = Y@W_in_h + bias; LN; @mlp_w; @W_out_h
//     -> g_th/g_tl bf16. grid (HH, BB), 256 thr.
// ============================================================
__global__ __launch_bounds__(256) void kB(const float* __restrict__ W_in,
                                          const float* __restrict__ b_in,
                                          const float* __restrict__ mlp_w,
                                          const float* __restrict__ ln_g,
                                          const float* __restrict__ ln_b,
                                          const float* __restrict__ W_out) {
    int h = blockIdx.x, b = blockIdx.y;
    __shared__ float bufA[4096];
    __shared__ float bufB[2048];
    __shared__ float bufC[2048];
    __shared__ float red[16];
    __shared__ float sred[32];
    int tid = threadIdx.x;

    // reduce inv_in chunk sums for this h (64 chunks x 32 g)
    if (tid < 32) {
        float t = 0.f;
#pragma unroll
        for (int ch = 0; ch < 64; ch++) t += g_sinp[ch * 256 + h * 32 + tid];
        sred[tid] = t;
    }
#pragma unroll
    for (int k = 0; k < 16; k++) {
        int idx = tid + k * 256;
        bufA[idx] = g_Y[((size_t)(b * HH + h)) * 4096 + idx];
    }
    __syncthreads();

    int d = tid & 63, g4 = tid >> 6;
    float sp[8];
#pragma unroll
    for (int k = 0; k < 8; k++) sp[k] = 0.f;
    for (int cc = 0; cc < 4; cc++) {
#pragma unroll
        for (int j = 0; j < 8; j++) {
            int idx = tid + j * 256;
            int r = idx >> 6, dd = idx & 63;
            bufB[idx] = W_in[((size_t)(cc * 32 + r)) * (HH * DHH) + h * 64 + dd];
        }
        __syncthreads();
#pragma unroll
        for (int i = 0; i < 32; i++) {
            float w = bufB[i * 64 + d];
            int c = cc * 32 + i;
#pragma unroll
            for (int k = 0; k < 8; k++) sp[k] += bufA[(g4 + 4 * k) * 128 + c] * w;
        }
        __syncthreads();
    }

    float bv = b_in[h * 64 + d];
#pragma unroll
    for (int k = 0; k < 8; k++) sp[k] += bv * sred[g4 + 4 * k];

    float lsum = 0.f, lsq = 0.f;
#pragma unroll
    for (int k = 0; k < 8; k++) { lsum += sp[k]; lsq += sp[k] * sp[k]; }
#pragma unroll
    for (int off = 16; off; off >>= 1) {
        lsum += __shfl_xor_sync(0xffffffffu, lsum, off);
        lsq  += __shfl_xor_sync(0xffffffffu, lsq,  off);
    }
    int warp = tid >> 5, lane = tid & 31;
    if (lane == 0) { red[warp] = lsum; red[8 + warp] = lsq; }
    __syncthreads();
    float tsum = 0.f, tsq = 0.f;
#pragma unroll
    for (int w = 0; w < 8; w++) { tsum += red[w]; tsq += red[8 + w]; }
    float mu = tsum * (1.f / 2048.f);
    float var = tsq * (1.f / 2048.f) - mu * mu;
    float rstd = rsqrtf(var + 1e-5f);
    __syncthreads();
#pragma unroll
    for (int k = 0; k < 8; k++) {
        int g = g4 + 4 * k;
        float v = (sp[k] - mu) * rstd * ln_g[g * 64 + d] + ln_b[g * 64 + d];
        bufB[g * 64 + d] = v;
    }
    __syncthreads();

#pragma unroll
    for (int j = 0; j < 16; j++) bufA[tid + j * 256] = mlp_w[tid + j * 256];
    __syncthreads();
    int o = d;
    float m[8];
#pragma unroll
    for (int k = 0; k < 8; k++) m[k] = 0.f;
#pragma unroll
    for (int dd = 0; dd < 64; dd++) {
        float w = bufA[dd * 64 + o];
#pragma unroll
        for (int k = 0; k < 8; k++) m[k] += bufB[(g4 + 4 * k) * 64 + dd] * w;
    }
#pragma unroll
    for (int k = 0; k < 8; k++) bufC[(g4 + 4 * k) * 64 + o] = m[k];
    __syncthreads();

    int c = tid & 127, g2 = tid >> 7;
    float tacc[16];
#pragma unroll
    for (int k = 0; k < 16; k++) tacc[k] = 0.f;
    for (int oc = 0; oc < 2; oc++) {
#pragma unroll
        for (int j = 0; j < 16; j++) {
            int idx = tid + j * 256;
            int r = idx >> 7, c2 = idx & 127;
            bufA[idx] = W_out[((size_t)(h * 64 + oc * 32 + r)) * CC + c2];
        }
        __syncthreads();
#pragma unroll
        for (int i = 0; i < 32; i++) {
            float w = bufA[i * 128 + c];
            int oo = oc * 32 + i;
#pragma unroll
            for (int k = 0; k < 16; k++) tacc[k] += bufC[(g2 + 2 * k) * 64 + oo] * w;
        }
        __syncthreads();
    }
    size_t tb = ((size_t)b * 256 + h * 32) * CC;
#pragma unroll
    for (int k = 0; k < 16; k++) {
        bf16 th, tl;
        sbf(tacc[k], th, tl);
        size_t off = tb + (size_t)(g2 + 2 * k) * CC + c;
        g_th[off] = th;
        g_tl[off] = tl;
    }
}

// ============================================================
// kD: decode GEMM: out[b][nt*128+m][c] = bias + A[n][hg] * B[hg][c], K=256.
// grid (64, BB), 256 thr, 3-stage ring.
// ============================================================
__global__ __launch_bounds__(256, 2) void kD(const float* __restrict__ b_out,
                                             float* __restrict__ out) {
    int tid = threadIdx.x, lane = tid & 31, wid = tid >> 5;
    int wm = wid & 3, wn = wid >> 2;
    int ntb = blockIdx.x, b = blockIdx.y;

    const bf16* Ah = g_Aoh + (size_t)(ntb * 128) * 256;
    const bf16* Al = g_Aol + (size_t)(ntb * 128) * 256;
    const bf16* Bh = g_th + (size_t)b * 256 * CC;
    const bf16* Bl = g_tl + (size_t)b * 256 * CC;

    float acc[2][8][4];
#pragma unroll
    for (int i = 0; i < 2; i++)
#pragma unroll
        for (int j = 0; j < 8; j++)
#pragma unroll
            for (int k = 0; k < 4; k++) acc[i][j][k] = 0.f;

    uint32_t sma = smem_u32(dsm);
    const int NST = 8;
    fill_stage(sma, Ah, Al, 256, Bh, Bl, tid);
    cpcommit();
    fill_stage(sma + STG, Ah + 32, Al + 32, 256,
               Bh + (size_t)32 * CC, Bl + (size_t)32 * CC, tid);
    cpcommit();
#pragma unroll 1
    for (int st = 0; st < NST; st++) {
        if (st + 2 < NST) {
            int nb = st + 2;
            fill_stage(sma + (nb % 3) * STG,
                       Ah + nb * 32, Al + nb * 32, 256,
                       Bh + (size_t)nb * 32 * CC, Bl + (size_t)nb * 32 * CC, tid);
            cpcommit();
            cpwait<2>();
        } else {
            cpwait<0>();
        }
        __syncthreads();
        compute_stage(sma + (st % 3) * STG, wm, wn, lane, acc);
        __syncthreads();
    }

    int g = lane >> 2, t4 = lane & 3;
#pragma unroll
    for (int mt = 0; mt < 2; mt++) {
#pragma unroll
        for (int nt = 0; nt < 8; nt++) {
            int rr = wm * 32 + mt * 16 + g;
            int cc = wn * 64 + nt * 8 + t4 * 2;
            float2 bo = *(const float2*)(b_out + cc);
            size_t row0 = ((size_t)b * NN + ntb * 128 + rr) * CC;
            float2 v0; v0.x = acc[mt][nt][0] + bo.x; v0.y = acc[mt][nt][1] + bo.y;
            *(float2*)(out + row0 + cc) = v0;
            float2 v1; v1.x = acc[mt][nt][2] + bo.x; v1.y = acc[mt][nt][3] + bo.y;
            *(float2*)(out + row0 + 8 * CC + cc) = v1;
        }
    }
}

// ============================================================
extern "C" void kernel_launch(void* const* d_in, const int* in_sizes, int n_in,
                              void* d_out, int out_size) {
    const float* x      = (const float*)d_in[0];
    const float* W_in   = (const float*)d_in[1];
    const float* b_in   = (const float*)d_in[2];
    const float* mlp_w  = (const float*)d_in[3];
    const float* ln_g   = (const float*)d_in[4];
    const float* ln_b   = (const float*)d_in[5];
    const float* W_out  = (const float*)d_in[6];
    const float* b_out  = (const float*)d_in[7];
    const float* inv_in = (const float*)d_in[8];
    const float* inv_out= (const float*)d_in[9];
    float* out = (float*)d_out;

    cudaFuncSetAttribute(kE, cudaFuncAttributeMaxDynamicSharedMemorySize, SMEM_DYN);
    cudaFuncSetAttribute(kD, cudaFuncAttributeMaxDynamicSharedMemorySize, SMEM_DYN);

    kPx<<<2048, 256>>>(x);
    kPin<<<dim3(8, 64), 256>>>(inv_in);
    kPout<<<64, 256>>>(inv_out);
    kE<<<dim3(2, SS, BB), 256, SMEM_DYN>>>();
    kR<<<256, 256>>>();
    kB<<<dim3(HH, BB), 256>>>(W_in, b_in, mlp_w, ln_g, ln_b, W_out);
    kD<<<dim3(64, BB), 256, SMEM_DYN>>>(b_out, out);
}

// round 6
// speedup vs baseline: 3.0023x; 1.1137x over previous
#include <cuda_runtime.h>
#include <cuda_bf16.h>
#include <cstdint>

// Problem constants
#define BB  8
#define NN  8192
#define CC  128
#define HH  8
#define DHH 64
#define GG  32
#define SS  16              // K-splits for encode phase
typedef unsigned long long u64;
typedef __nv_bfloat16 bf16;

// -------- global scratch (no allocation allowed) --------
__device__ bf16  g_xh [(size_t)BB*NN*CC];    // x hi  [b][n][c]
__device__ bf16  g_xl [(size_t)BB*NN*CC];    // x lo
__device__ bf16  g_Ath[(size_t)256*NN];      // inv_in^T hi [hg][n]
__device__ bf16  g_Atl[(size_t)256*NN];
__device__ bf16  g_Aoh[(size_t)NN*256];      // inv_out hi [n][hg]
__device__ bf16  g_Aol[(size_t)NN*256];
__device__ bf16  g_th [(size_t)BB*256*CC];   // middle out hi [b][hg][c]
__device__ bf16  g_tl [(size_t)BB*256*CC];
__device__ float g_Yp [(size_t)SS*BB*256*CC];// encode fp32 partials
__device__ float g_sinp[64*HH*GG];           // 64-chunk partials of sum_n inv_in

// -------- small helpers --------
__device__ __forceinline__ uint32_t smem_u32(const void* p) {
    uint32_t a;
    asm("{ .reg .u64 t; cvta.to.shared.u64 t, %1; cvt.u32.u64 %0, t; }" : "=r"(a) : "l"(p));
    return a;
}
__device__ __forceinline__ void sbf(float v, bf16& h, bf16& l) {
    h = __float2bfloat16(v);
    l = __float2bfloat16(v - __bfloat162float(h));
}
__device__ __forceinline__ uint32_t bp(bf16 a, bf16 b) {
    return (uint32_t)__bfloat16_as_ushort(a) | ((uint32_t)__bfloat16_as_ushort(b) << 16);
}
__device__ __forceinline__ void cpa16(uint32_t dst, const void* src) {
    asm volatile("cp.async.cg.shared.global [%0], [%1], 16;" :: "r"(dst), "l"(src));
}
__device__ __forceinline__ void cpcommit() { asm volatile("cp.async.commit_group;" ::: "memory"); }
template<int N> __device__ __forceinline__ void cpwait() {
    asm volatile("cp.async.wait_group %0;" :: "n"(N) : "memory");
}
__device__ __forceinline__ void ldm4(uint32_t* r, uint32_t a) {
    asm volatile("ldmatrix.sync.aligned.m8n8.x4.shared.b16 {%0,%1,%2,%3}, [%4];"
                 : "=r"(r[0]), "=r"(r[1]), "=r"(r[2]), "=r"(r[3]) : "r"(a));
}
__device__ __forceinline__ void ldm4t(uint32_t* r, uint32_t a) {
    asm volatile("ldmatrix.sync.aligned.m8n8.x4.trans.shared.b16 {%0,%1,%2,%3}, [%4];"
                 : "=r"(r[0]), "=r"(r[1]), "=r"(r[2]), "=r"(r[3]) : "r"(a));
}
__device__ __forceinline__ void mma16816(float* d, const uint32_t* a, const uint32_t* b) {
    asm volatile(
        "mma.sync.aligned.m16n8k16.row.col.f32.bf16.bf16.f32 "
        "{%0,%1,%2,%3}, {%4,%5,%6,%7}, {%8,%9}, {%0,%1,%2,%3};"
        : "+f"(d[0]), "+f"(d[1]), "+f"(d[2]), "+f"(d[3])
        : "r"(a[0]), "r"(a[1]), "r"(a[2]), "r"(a[3]), "r"(b[0]), "r"(b[1]));
}

// smem stage layout (bytes)
#define OFFAH 0
#define OFFAL 8192
#define OFFBH 16384
#define OFFBL 24576
#define STG   32768
#define SMEM_DYN (3*STG)

// A tile: 128 rows x 32 k bf16, row=64B=4 chunks, phys chunk = kc ^ ((r>>1)&3)
__device__ __forceinline__ uint32_t offA(int r, int kc) {
    return (uint32_t)(r * 64 + ((kc ^ ((r >> 1) & 3)) << 4));
}
// B tile: 32 k rows x 128 n bf16, row=256B=16 chunks, phys chunk = nc ^ (r&7)
__device__ __forceinline__ uint32_t offB(int r, int nc) {
    return (uint32_t)(r * 256 + ((nc ^ (r & 7)) << 4));
}

// fill one stage: A (hi/lo) and B (hi/lo). 8 cp.async per thread.
__device__ __forceinline__ void fill_stage(uint32_t sma,
        const bf16* Ah, const bf16* Al, size_t sA,
        const bf16* Bh, const bf16* Bl, int tid) {
#pragma unroll
    for (int i = 0; i < 2; i++) {
        int idx = tid + i * 256;           // 0..511
        int r = idx >> 2, kc = idx & 3;
        uint32_t o = offA(r, kc);
        const bf16* sa = Ah + (size_t)r * sA + kc * 8;
        const bf16* sl = Al + (size_t)r * sA + kc * 8;
        cpa16(sma + OFFAH + o, sa);
        cpa16(sma + OFFAL + o, sl);
    }
#pragma unroll
    for (int i = 0; i < 2; i++) {
        int idx = tid + i * 256;
        int r = idx >> 4, nc = idx & 15;
        uint32_t o = offB(r, nc);
        cpa16(sma + OFFBH + o, Bh + r * CC + nc * 8);
        cpa16(sma + OFFBL + o, Bl + r * CC + nc * 8);
    }
}

// compute one BK=32 stage: 2 k16 halves, 3-term split
__device__ __forceinline__ void compute_stage(uint32_t sma, int wm, int wn, int lane,
                                              float acc[2][8][4]) {
#pragma unroll
    for (int kk = 0; kk < 2; kk++) {
        uint32_t ah[2][4], al[2][4];
        int arow = wm * 32 + (lane & 15);
        int akc = kk * 2 + (lane >> 4);
#pragma unroll
        for (int mt = 0; mt < 2; mt++) {
            int r = arow + mt * 16;
            uint32_t o = offA(r, akc);
            ldm4(ah[mt], sma + OFFAH + o);
            ldm4(al[mt], sma + OFFAL + o);
        }
        int brow = kk * 16 + (lane & 15);
#pragma unroll
        for (int ng = 0; ng < 4; ng++) {
            uint32_t bh[4], bl[4];
            int nc = wn * 8 + ng * 2 + (lane >> 4);
            uint32_t o = offB(brow, nc);
            ldm4t(bh, sma + OFFBH + o);
            ldm4t(bl, sma + OFFBL + o);
#pragma unroll
            for (int mt = 0; mt < 2; mt++) {
#pragma unroll
                for (int s2 = 0; s2 < 2; s2++) {
                    float* d = acc[mt][ng * 2 + s2];
                    mma16816(d, ah[mt], bh + s2 * 2);
                    mma16816(d, ah[mt], bl + s2 * 2);
                    mma16816(d, al[mt], bh + s2 * 2);
                }
            }
        }
    }
}

// ============================================================
// kPx: x -> bf16 hi/lo
// ============================================================
__global__ __launch_bounds__(256) void kPx(const float* __restrict__ x) {
    const float4* src = (const float4*)x;
#pragma unroll
    for (int i = 0; i < 4; i++) {
        size_t idx = (size_t)blockIdx.x * 1024 + i * 256 + threadIdx.x;  // float4 idx
        float4 v = src[idx];
        bf16 hx, lx, hy, ly, hz, lz, hw, lw;
        sbf(v.x, hx, lx); sbf(v.y, hy, ly); sbf(v.z, hz, lz); sbf(v.w, hw, lw);
        uint2 ph; ph.x = bp(hx, hy); ph.y = bp(hz, hw);
        uint2 pl; pl.x = bp(lx, ly); pl.y = bp(lz, lw);
        ((uint2*)g_xh)[idx] = ph;
        ((uint2*)g_xl)[idx] = pl;
    }
}

// ============================================================
// kP: basis conversion. grid (8, 64, 2), 256 thr.
//   z=0: inv_in [h][n][g] -> At[hg][n] hi/lo  + chunk sums
//   z=1: inv_out [h][n][g] -> Ao[n][hg] hi/lo
// ============================================================
__global__ __launch_bounds__(256) void kP(const float* __restrict__ inv_in,
                                          const float* __restrict__ inv_out) {
    __shared__ float s[128][33];
    __shared__ float ps[32][9];
    int h = blockIdx.x, nb = blockIdx.y * 128, tid = threadIdx.x;
    if (blockIdx.z == 0) {
        const float4* src = (const float4*)(inv_in + ((size_t)h * NN + nb) * GG);
#pragma unroll
        for (int i = 0; i < 4; i++) {
            int f = tid + i * 256;
            int n = f >> 3, q = f & 7;
            float4 v = src[f];
            s[n][q * 4] = v.x; s[n][q * 4 + 1] = v.y; s[n][q * 4 + 2] = v.z; s[n][q * 4 + 3] = v.w;
        }
        __syncthreads();
        int g = tid >> 3, j = tid & 7;
        uint4 uh[2], ul[2];
        bf16* ph = (bf16*)uh;
        bf16* pl = (bf16*)ul;
        float psum = 0.f;
#pragma unroll
        for (int i = 0; i < 16; i++) {
            float v = s[j * 16 + i][g];
            psum += v;
            sbf(v, ph[i], pl[i]);
        }
        size_t off = ((size_t)(h * 32 + g)) * NN + nb + j * 16;
        *(uint4*)(g_Ath + off) = uh[0]; *(uint4*)(g_Ath + off + 8) = uh[1];
        *(uint4*)(g_Atl + off) = ul[0]; *(uint4*)(g_Atl + off + 8) = ul[1];
        ps[g][j] = psum;
        __syncthreads();
        if (tid < 32) {
            float t = 0.f;
#pragma unroll
            for (int jj = 0; jj < 8; jj++) t += ps[tid][jj];
            g_sinp[blockIdx.y * 256 + h * 32 + tid] = t;
        }
    } else {
        const float4* src = (const float4*)(inv_out + ((size_t)h * NN + nb) * GG);
#pragma unroll
        for (int i = 0; i < 4; i++) {
            int f = tid + i * 256;
            int n = f >> 3, q = f & 7;
            float4 v = src[f];
            s[n][q * 4] = v.x; s[n][q * 4 + 1] = v.y; s[n][q * 4 + 2] = v.z; s[n][q * 4 + 3] = v.w;
        }
        __syncthreads();
        int n = tid >> 1, half = tid & 1;
        uint4 uh[2], ul[2];
        bf16* ph = (bf16*)uh;
        bf16* pl = (bf16*)ul;
#pragma unroll
        for (int i = 0; i < 16; i++) sbf(s[n][half * 16 + i], ph[i], pl[i]);
        size_t off = ((size_t)(nb + n)) * 256 + h * 32 + half * 16;
        *(uint4*)(g_Aoh + off) = uh[0]; *(uint4*)(g_Aoh + off + 8) = uh[1];
        *(uint4*)(g_Aol + off) = ul[0]; *(uint4*)(g_Aol + off + 8) = ul[1];
    }
}

// ============================================================
// kE: encode GEMM partials. grid (2, SS, BB), 256 thr.
// 3-stage ring, ONE sync per stage.
// ============================================================
extern __shared__ char dsm[];
__global__ __launch_bounds__(256, 2) void kE() {
    int tid = threadIdx.x, lane = tid & 31, wid = tid >> 5;
    int wm = wid & 3, wn = wid >> 2;
    int mhalf = blockIdx.x, s = blockIdx.y, b = blockIdx.z;

    const bf16* Ah = g_Ath + (size_t)(mhalf * 128) * NN + s * 512;
    const bf16* Al = g_Atl + (size_t)(mhalf * 128) * NN + s * 512;
    const bf16* Bh = g_xh + ((size_t)b * NN + s * 512) * CC;
    const bf16* Bl = g_xl + ((size_t)b * NN + s * 512) * CC;

    float acc[2][8][4];
#pragma unroll
    for (int i = 0; i < 2; i++)
#pragma unroll
        for (int j = 0; j < 8; j++)
#pragma unroll
            for (int k = 0; k < 4; k++) acc[i][j][k] = 0.f;

    uint32_t sma = smem_u32(dsm);
    const int NST = 16;
    fill_stage(sma, Ah, Al, NN, Bh, Bl, tid);
    cpcommit();
    fill_stage(sma + STG, Ah + 32, Al + 32, NN,
               Bh + (size_t)32 * CC, Bl + (size_t)32 * CC, tid);
    cpcommit();
#pragma unroll 1
    for (int st = 0; st < NST; st++) {
        if (st < NST - 2) cpwait<1>(); else cpwait<0>();
        __syncthreads();
        compute_stage(sma + (st % 3) * STG, wm, wn, lane, acc);
        if (st + 2 < NST) {
            int nb = st + 2;
            fill_stage(sma + (nb % 3) * STG,
                       Ah + nb * 32, Al + nb * 32, NN,
                       Bh + (size_t)nb * 32 * CC, Bl + (size_t)nb * 32 * CC, tid);
            cpcommit();
        }
    }

    int g = lane >> 2, t4 = lane & 3;
    size_t base = (((size_t)s * BB + b) * 256 + mhalf * 128);
#pragma unroll
    for (int mt = 0; mt < 2; mt++) {
#pragma unroll
        for (int nt = 0; nt < 8; nt++) {
            int rr = wm * 32 + mt * 16 + g;
            int cc = wn * 64 + nt * 8 + t4 * 2;
            float2 v0; v0.x = acc[mt][nt][0]; v0.y = acc[mt][nt][1];
            *(float2*)(g_Yp + (base + rr) * CC + cc) = v0;
            float2 v1; v1.x = acc[mt][nt][2]; v1.y = acc[mt][nt][3];
            *(float2*)(g_Yp + (base + rr + 8) * CC + cc) = v1;
        }
    }
}

// ============================================================
// kB: middle per (b,h): reduce Yp; spec = Y@W_in_h + bias; LN; @mlp_w;
//     @W_out_h -> g_th/g_tl bf16. grid (HH, BB), 512 thr.
// ============================================================
__global__ __launch_bounds__(512) void kB(const float* __restrict__ W_in,
                                          const float* __restrict__ b_in,
                                          const float* __restrict__ mlp_w,
                                          const float* __restrict__ ln_g,
                                          const float* __restrict__ ln_b,
                                          const float* __restrict__ W_out) {
    int h = blockIdx.x, b = blockIdx.y;
    __shared__ float bufA[4096];
    __shared__ float bufB[2048];
    __shared__ float bufC[2048];
    __shared__ float red[32];
    __shared__ float sred[32];
    int tid = threadIdx.x;

    // reduce inv_in chunk sums for this h
    if (tid < 32) {
        float t = 0.f;
#pragma unroll
        for (int ch = 0; ch < 64; ch++) t += g_sinp[ch * 256 + h * 32 + tid];
        sred[tid] = t;
    }
    // S1: reduce Yp splits directly (fused kR): 4096 elems / 512 thr
#pragma unroll
    for (int k = 0; k < 8; k++) {
        int idx = tid + k * 512;
        float ssum = 0.f;
#pragma unroll
        for (int ss = 0; ss < SS; ss++)
            ssum += g_Yp[(((size_t)ss * BB + b) * 256 + h * 32) * CC + idx];
        bufA[idx] = ssum;
    }
    __syncthreads();

    // S2: spec_raw[g][d] = sum_c Y[g][c] * W_in[c][h*64+d]; g = g8 + 8k, k<4
    int d = tid & 63, g8 = tid >> 6;
    float sp[4];
#pragma unroll
    for (int k = 0; k < 4; k++) sp[k] = 0.f;
    for (int cc = 0; cc < 4; cc++) {
#pragma unroll
        for (int j = 0; j < 4; j++) {
            int idx = tid + j * 512;
            int r = idx >> 6, dd = idx & 63;
            bufB[idx] = W_in[((size_t)(cc * 32 + r)) * (HH * DHH) + h * 64 + dd];
        }
        __syncthreads();
#pragma unroll
        for (int i = 0; i < 32; i++) {
            float w = bufB[i * 64 + d];
            int c = cc * 32 + i;
#pragma unroll
            for (int k = 0; k < 4; k++) sp[k] += bufA[(g8 + 8 * k) * 128 + c] * w;
        }
        __syncthreads();
    }

    float bv = b_in[h * 64 + d];
#pragma unroll
    for (int k = 0; k < 4; k++) sp[k] += bv * sred[g8 + 8 * k];

    // LayerNorm over all 2048 (g,d)
    float lsum = 0.f, lsq = 0.f;
#pragma unroll
    for (int k = 0; k < 4; k++) { lsum += sp[k]; lsq += sp[k] * sp[k]; }
#pragma unroll
    for (int off = 16; off; off >>= 1) {
        lsum += __shfl_xor_sync(0xffffffffu, lsum, off);
        lsq  += __shfl_xor_sync(0xffffffffu, lsq,  off);
    }
    int warp = tid >> 5, lane = tid & 31;
    if (lane == 0) { red[warp] = lsum; red[16 + warp] = lsq; }
    __syncthreads();
    float tsum = 0.f, tsq = 0.f;
#pragma unroll
    for (int w = 0; w < 16; w++) { tsum += red[w]; tsq += red[16 + w]; }
    float mu = tsum * (1.f / 2048.f);
    float var = tsq * (1.f / 2048.f) - mu * mu;
    float rstd = rsqrtf(var + 1e-5f);
    __syncthreads();
#pragma unroll
    for (int k = 0; k < 4; k++) {
        int g = g8 + 8 * k;
        float v = (sp[k] - mu) * rstd * ln_g[g * 64 + d] + ln_b[g * 64 + d];
        bufB[g * 64 + d] = v;
    }
    __syncthreads();

    // S4: m[g][o] = sum_d spec_n[g][d] * mlp_w[d][o]
#pragma unroll
    for (int j = 0; j < 8; j++) bufA[tid + j * 512] = mlp_w[tid + j * 512];
    __syncthreads();
    int o = d;
    float m[4];
#pragma unroll
    for (int k = 0; k < 4; k++) m[k] = 0.f;
#pragma unroll
    for (int dd = 0; dd < 64; dd++) {
        float w = bufA[dd * 64 + o];
#pragma unroll
        for (int k = 0; k < 4; k++) m[k] += bufB[(g8 + 8 * k) * 64 + dd] * w;
    }
#pragma unroll
    for (int k = 0; k < 4; k++) bufC[(g8 + 8 * k) * 64 + o] = m[k];
    __syncthreads();

    // S5: t[g][c] = sum_o m[g][o] * W_out[h*64+o][c]; g = g4 + 4k, k<8
    int c = tid & 127, g4 = tid >> 7;
    float tacc[8];
#pragma unroll
    for (int k = 0; k < 8; k++) tacc[k] = 0.f;
    for (int oc = 0; oc < 2; oc++) {
#pragma unroll
        for (int j = 0; j < 8; j++) {
            int idx = tid + j * 512;
            int r = idx >> 7, c2 = idx & 127;
            bufA[idx] = W_out[((size_t)(h * 64 + oc * 32 + r)) * CC + c2];
        }
        __syncthreads();
#pragma unroll
        for (int i = 0; i < 32; i++) {
            float w = bufA[i * 128 + c];
            int oo = oc * 32 + i;
#pragma unroll
            for (int k = 0; k < 8; k++) tacc[k] += bufC[(g4 + 4 * k) * 64 + oo] * w;
        }
        __syncthreads();
    }
    size_t tb = ((size_t)b * 256 + h * 32) * CC;
#pragma unroll
    for (int k = 0; k < 8; k++) {
        bf16 th, tl;
        sbf(tacc[k], th, tl);
        size_t off = tb + (size_t)(g4 + 4 * k) * CC + c;
        g_th[off] = th;
        g_tl[off] = tl;
    }
}

// ============================================================
// kD: decode GEMM: out[b][nt*128+m][c] = bias + A[n][hg] * B[hg][c], K=256.
// grid (64, BB), 256 thr, 3-stage ring, ONE sync per stage.
// ============================================================
__global__ __launch_bounds__(256, 2) void kD(const float* __restrict__ b_out,
                                             float* __restrict__ out) {
    int tid = threadIdx.x, lane = tid & 31, wid = tid >> 5;
    int wm = wid & 3, wn = wid >> 2;
    int ntb = blockIdx.x, b = blockIdx.y;

    const bf16* Ah = g_Aoh + (size_t)(ntb * 128) * 256;
    const bf16* Al = g_Aol + (size_t)(ntb * 128) * 256;
    const bf16* Bh = g_th + (size_t)b * 256 * CC;
    const bf16* Bl = g_tl + (size_t)b * 256 * CC;

    float acc[2][8][4];
#pragma unroll
    for (int i = 0; i < 2; i++)
#pragma unroll
        for (int j = 0; j < 8; j++)
#pragma unroll
            for (int k = 0; k < 4; k++) acc[i][j][k] = 0.f;

    uint32_t sma = smem_u32(dsm);
    const int NST = 8;
    fill_stage(sma, Ah, Al, 256, Bh, Bl, tid);
    cpcommit();
    fill_stage(sma + STG, Ah + 32, Al + 32, 256,
               Bh + (size_t)32 * CC, Bl + (size_t)32 * CC, tid);
    cpcommit();
#pragma unroll 1
    for (int st = 0; st < NST; st++) {
        if (st < NST - 2) cpwait<1>(); else cpwait<0>();
        __syncthreads();
        compute_stage(sma + (st % 3) * STG, wm, wn, lane, acc);
        if (st + 2 < NST) {
            int nb = st + 2;
            fill_stage(sma + (nb % 3) * STG,
                       Ah + nb * 32, Al + nb * 32, 256,
                       Bh + (size_t)nb * 32 * CC, Bl + (size_t)nb * 32 * CC, tid);
            cpcommit();
        }
    }

    int g = lane >> 2, t4 = lane & 3;
#pragma unroll
    for (int mt = 0; mt < 2; mt++) {
#pragma unroll
        for (int nt = 0; nt < 8; nt++) {
            int rr = wm * 32 + mt * 16 + g;
            int cc = wn * 64 + nt * 8 + t4 * 2;
            float2 bo = *(const float2*)(b_out + cc);
            size_t row0 = ((size_t)b * NN + ntb * 128 + rr) * CC;
            float2 v0; v0.x = acc[mt][nt][0] + bo.x; v0.y = acc[mt][nt][1] + bo.y;
            *(float2*)(out + row0 + cc) = v0;
            float2 v1; v1.x = acc[mt][nt][2] + bo.x; v1.y = acc[mt][nt][3] + bo.y;
            *(float2*)(out + row0 + 8 * CC + cc) = v1;
        }
    }
}

// ============================================================
extern "C" void kernel_launch(void* const* d_in, const int* in_sizes, int n_in,
                              void* d_out, int out_size) {
    const float* x      = (const float*)d_in[0];
    const float* W_in   = (const float*)d_in[1];
    const float* b_in   = (const float*)d_in[2];
    const float* mlp_w  = (const float*)d_in[3];
    const float* ln_g   = (const float*)d_in[4];
    const float* ln_b   = (const float*)d_in[5];
    const float* W_out  = (const float*)d_in[6];
    const float* b_out  = (const float*)d_in[7];
    const float* inv_in = (const float*)d_in[8];
    const float* inv_out= (const float*)d_in[9];
    float* out = (float*)d_out;

    cudaFuncSetAttribute(kE, cudaFuncAttributeMaxDynamicSharedMemorySize, SMEM_DYN);
    cudaFuncSetAttribute(kD, cudaFuncAttributeMaxDynamicSharedMemorySize, SMEM_DYN);

    kPx<<<2048, 256>>>(x);
    kP<<<dim3(8, 64, 2), 256>>>(inv_in, inv_out);
    kE<<<dim3(2, SS, BB), 256, SMEM_DYN>>>();
    kB<<<dim3(HH, BB), 512>>>(W_in, b_in, mlp_w, ln_g, ln_b, W_out);
    kD<<<dim3(64, BB), 256, SMEM_DYN>>>(b_out, out);
}